// round 1
// baseline (speedup 1.0000x reference)
#include <cuda_runtime.h>
#include <math.h>

#define EMBED 768
#define B_Q   256
#define N_TOT 16384
#define SCALE 0.1020620726159657f   // 96^-0.5

// Scratch (allowed: __device__ globals, no runtime allocation)
__device__ float g_q[B_Q * EMBED];     // 0.75 MB
__device__ float g_k[N_TOT * EMBED];   // 48 MB

// ---------------------------------------------------------------------------
// Projection GEMM: out[m][e] = sum_k A[m][k] * W[e][k] + bias[e]
// Tiles 128x128x8, 256 threads, 8x8 microtile, fp32.
// grid.y in [0,128): k-projection (search,Wk,bk -> g_k), m0 = by*128
// grid.y in [128,130): q-projection (query,Wq,bq -> g_q), m0 = (by-128)*128
// grid.x in [0,6): e-tile (768/128)
// ---------------------------------------------------------------------------
__global__ __launch_bounds__(256, 2)
void proj_kernel(const float* __restrict__ query, const float* __restrict__ Wq,
                 const float* __restrict__ bq,
                 const float* __restrict__ search, const float* __restrict__ Wk,
                 const float* __restrict__ bk)
{
    __shared__ float As[8][132];
    __shared__ float Bs[8][132];

    const int tid = threadIdx.x;
    const int tx  = tid & 15;
    const int ty  = tid >> 4;

    const int by = blockIdx.y;
    const float *A, *W, *bias;
    float* out;
    int m0;
    if (by < 128) { A = search; W = Wk; bias = bk; out = g_k; m0 = by * 128; }
    else          { A = query;  W = Wq; bias = bq; out = g_q; m0 = (by - 128) * 128; }
    const int n0 = blockIdx.x * 128;

    const int lrow = tid >> 1;        // 0..127
    const int lseg = (tid & 1) * 4;   // 0 or 4

    const float* Aptr = A + (size_t)(m0 + lrow) * EMBED + lseg;
    const float* Wptr = W + (size_t)(n0 + lrow) * EMBED + lseg;

    float acc[8][8];
#pragma unroll
    for (int i = 0; i < 8; ++i)
#pragma unroll
        for (int j = 0; j < 8; ++j) acc[i][j] = 0.0f;

    float4 pa = *(const float4*)(Aptr);
    float4 pb = *(const float4*)(Wptr);

    const int KT = EMBED / 8;  // 96
    for (int kt = 0; kt < KT; ++kt) {
        As[lseg + 0][lrow] = pa.x;
        As[lseg + 1][lrow] = pa.y;
        As[lseg + 2][lrow] = pa.z;
        As[lseg + 3][lrow] = pa.w;
        Bs[lseg + 0][lrow] = pb.x;
        Bs[lseg + 1][lrow] = pb.y;
        Bs[lseg + 2][lrow] = pb.z;
        Bs[lseg + 3][lrow] = pb.w;
        __syncthreads();

        if (kt + 1 < KT) {
            pa = *(const float4*)(Aptr + (kt + 1) * 8);
            pb = *(const float4*)(Wptr + (kt + 1) * 8);
        }

#pragma unroll
        for (int kk = 0; kk < 8; ++kk) {
            float a[8], b[8];
            *(float4*)&a[0] = *(const float4*)&As[kk][ty * 4];
            *(float4*)&a[4] = *(const float4*)&As[kk][64 + ty * 4];
            *(float4*)&b[0] = *(const float4*)&Bs[kk][tx * 4];
            *(float4*)&b[4] = *(const float4*)&Bs[kk][64 + tx * 4];
#pragma unroll
            for (int i = 0; i < 8; ++i)
#pragma unroll
                for (int j = 0; j < 8; ++j)
                    acc[i][j] = fmaf(a[i], b[j], acc[i][j]);
        }
        __syncthreads();
    }

    // Epilogue: add bias, write float4 x2 per row of the microtile.
    float4 bv0 = *(const float4*)(bias + n0 + tx * 4);
    float4 bv1 = *(const float4*)(bias + n0 + 64 + tx * 4);
#pragma unroll
    for (int i = 0; i < 8; ++i) {
        const int m = m0 + ((i < 4) ? (ty * 4 + i) : (64 + ty * 4 + (i - 4)));
        float4 r0 = make_float4(acc[i][0] + bv0.x, acc[i][1] + bv0.y,
                                acc[i][2] + bv0.z, acc[i][3] + bv0.w);
        float4 r1 = make_float4(acc[i][4] + bv1.x, acc[i][5] + bv1.y,
                                acc[i][6] + bv1.z, acc[i][7] + bv1.w);
        *(float4*)(out + (size_t)m * EMBED + n0 + tx * 4)      = r0;
        *(float4*)(out + (size_t)m * EMBED + n0 + 64 + tx * 4) = r1;
    }
}

// ---------------------------------------------------------------------------
// Attention + fused MLP head.
// Per block: 64 (b) x 64 (n) outputs. Loop over K=768 in 16-deep chunks
// (6 chunks per head). Per-head logit accumulators fold into 4 persistent
// accumulators hp[..][j] via SCALE*W1[j,h] at each head boundary.
// Epilogue: x = hp + b1; gelu_exact(x); out = b2 + W2 . gelu.
// grid = (4 b-tiles, 256 n-tiles) : b fastest so concurrent blocks share K
// tiles via L2.
// ---------------------------------------------------------------------------
__global__ __launch_bounds__(256, 2)
void attn_kernel(const float* __restrict__ W1, const float* __restrict__ b1,
                 const float* __restrict__ W2, const float* __restrict__ b2,
                 float* __restrict__ out)
{
    __shared__ float Qs[16][68];
    __shared__ float Ks[16][68];
    __shared__ float s_w1[32];
    __shared__ float s_b1[4];
    __shared__ float s_w2[4];
    __shared__ float s_b2;

    const int tid = threadIdx.x;
    const int tx  = tid & 15;
    const int ty  = tid >> 4;
    const int b0  = blockIdx.x * 64;
    const int n0  = blockIdx.y * 64;

    if (tid < 32) s_w1[tid] = W1[tid] * SCALE;   // W1 is (4,8) row-major
    if (tid < 4)  { s_b1[tid] = b1[tid]; s_w2[tid] = W2[tid]; }
    if (tid == 0) s_b2 = b2[0];

    const int lrow = tid >> 2;        // 0..63
    const int lseg = (tid & 3) * 4;   // 0,4,8,12

    const float* qptr = g_q + (size_t)(b0 + lrow) * EMBED + lseg;
    const float* kptr = g_k + (size_t)(n0 + lrow) * EMBED + lseg;

    float hp[4][4][4];
#pragma unroll
    for (int i = 0; i < 4; ++i)
#pragma unroll
        for (int j = 0; j < 4; ++j)
#pragma unroll
            for (int jj = 0; jj < 4; ++jj) hp[i][j][jj] = 0.0f;

    float acc[4][4];
#pragma unroll
    for (int i = 0; i < 4; ++i)
#pragma unroll
        for (int j = 0; j < 4; ++j) acc[i][j] = 0.0f;

    float4 pq = *(const float4*)qptr;
    float4 pk = *(const float4*)kptr;

    for (int c = 0; c < 48; ++c) {   // 48 chunks of 16 = K=768; 6 per head
        Qs[lseg + 0][lrow] = pq.x;
        Qs[lseg + 1][lrow] = pq.y;
        Qs[lseg + 2][lrow] = pq.z;
        Qs[lseg + 3][lrow] = pq.w;
        Ks[lseg + 0][lrow] = pk.x;
        Ks[lseg + 1][lrow] = pk.y;
        Ks[lseg + 2][lrow] = pk.z;
        Ks[lseg + 3][lrow] = pk.w;
        __syncthreads();

        if (c + 1 < 48) {
            pq = *(const float4*)(qptr + (c + 1) * 16);
            pk = *(const float4*)(kptr + (c + 1) * 16);
        }

#pragma unroll
        for (int kk = 0; kk < 16; ++kk) {
            float4 a = *(const float4*)&Qs[kk][ty * 4];
            float4 b = *(const float4*)&Ks[kk][tx * 4];
            float av[4] = {a.x, a.y, a.z, a.w};
            float bv[4] = {b.x, b.y, b.z, b.w};
#pragma unroll
            for (int i = 0; i < 4; ++i)
#pragma unroll
                for (int j = 0; j < 4; ++j)
                    acc[i][j] = fmaf(av[i], bv[j], acc[i][j]);
        }
        __syncthreads();

        if ((c % 6) == 5) {  // head boundary: fold SCALE*W1[:,h] into hp
            const int h = c / 6;
            const float w0 = s_w1[0 * 8 + h];
            const float w1v = s_w1[1 * 8 + h];
            const float w2v = s_w1[2 * 8 + h];
            const float w3 = s_w1[3 * 8 + h];
#pragma unroll
            for (int i = 0; i < 4; ++i)
#pragma unroll
                for (int j = 0; j < 4; ++j) {
                    const float v = acc[i][j];
                    hp[i][j][0] = fmaf(w0,  v, hp[i][j][0]);
                    hp[i][j][1] = fmaf(w1v, v, hp[i][j][1]);
                    hp[i][j][2] = fmaf(w2v, v, hp[i][j][2]);
                    hp[i][j][3] = fmaf(w3,  v, hp[i][j][3]);
                    acc[i][j] = 0.0f;
                }
        }
    }

    // Epilogue: exact GELU (erf) + W2 reduction + biases; coalesced float4 out.
    const float inv_sqrt2 = 0.70710678118654752f;
#pragma unroll
    for (int i = 0; i < 4; ++i) {
        float r[4];
#pragma unroll
        for (int j = 0; j < 4; ++j) {
            float s = s_b2;
#pragma unroll
            for (int jj = 0; jj < 4; ++jj) {
                float x = hp[i][j][jj] + s_b1[jj];
                float g = 0.5f * x * (1.0f + erff(x * inv_sqrt2));
                s = fmaf(s_w2[jj], g, s);
            }
            r[j] = s;
        }
        *(float4*)(out + (size_t)(b0 + ty * 4 + i) * N_TOT + n0 + tx * 4) =
            make_float4(r[0], r[1], r[2], r[3]);
    }
}

// ---------------------------------------------------------------------------
extern "C" void kernel_launch(void* const* d_in, const int* in_sizes, int n_in,
                              void* d_out, int out_size)
{
    const float* query  = (const float*)d_in[0];
    const float* search = (const float*)d_in[1];
    const float* Wq     = (const float*)d_in[2];
    const float* bq     = (const float*)d_in[3];
    const float* Wk     = (const float*)d_in[4];
    const float* bk     = (const float*)d_in[5];
    const float* W1     = (const float*)d_in[6];
    const float* b1     = (const float*)d_in[7];
    const float* W2     = (const float*)d_in[8];
    const float* b2     = (const float*)d_in[9];
    float* out = (float*)d_out;

    // Both projections in one launch: by 0..127 = K-proj, by 128..129 = Q-proj
    proj_kernel<<<dim3(6, 130), 256>>>(query, Wq, bq, search, Wk, bk);

    // Fused logits + MLP head
    attn_kernel<<<dim3(4, 256), 256>>>(W1, b1, W2, b2, out);
}

// round 3
// speedup vs baseline: 1.8085x; 1.8085x over previous
#include <cuda_runtime.h>
#include <cuda_bf16.h>
#include <cstdint>
#include <math.h>

#define EMBED 768
#define BQ    256
#define NTOT  16384
#define SCALE 0.1020620726159657f   // 96^-0.5

// ---------------------------------------------------------------------------
// Device scratch (static globals — no runtime allocation)
// ---------------------------------------------------------------------------
__device__ __nv_bfloat16 g_sh_hi[NTOT*EMBED], g_sh_lo[NTOT*EMBED];    // search split
__device__ __nv_bfloat16 g_qi_hi[BQ*EMBED],   g_qi_lo[BQ*EMBED];      // query split
__device__ __nv_bfloat16 g_wk_hi[EMBED*EMBED], g_wk_lo[EMBED*EMBED];  // Wk split
__device__ __nv_bfloat16 g_wq_hi[EMBED*EMBED], g_wq_lo[EMBED*EMBED];  // Wq split
__device__ __nv_bfloat16 g_k_hi[NTOT*EMBED],  g_k_lo[NTOT*EMBED];     // projected K split
__device__ __nv_bfloat16 g_qp_hi[BQ*EMBED],   g_qp_lo[BQ*EMBED];      // projected Q split

// ---------------------------------------------------------------------------
// Helpers
// ---------------------------------------------------------------------------
__device__ __forceinline__ uint32_t smem_u32(const void* p) {
    uint32_t a;
    asm("{ .reg .u64 t; cvta.to.shared.u64 t, %1; cvt.u32.u64 %0, t; }"
        : "=r"(a) : "l"(p));
    return a;
}

__device__ __forceinline__ void cp16(uint32_t dst, const void* src) {
    asm volatile("cp.async.cg.shared.global [%0], [%1], 16;" :: "r"(dst), "l"(src));
}
#define CP_COMMIT() asm volatile("cp.async.commit_group;")
#define CP_WAIT0()  asm volatile("cp.async.wait_group 0;")

__device__ __forceinline__ void ldm_x4(uint32_t& r0, uint32_t& r1, uint32_t& r2,
                                       uint32_t& r3, uint32_t addr) {
    asm volatile("ldmatrix.sync.aligned.m8n8.x4.shared.b16 {%0,%1,%2,%3}, [%4];"
                 : "=r"(r0), "=r"(r1), "=r"(r2), "=r"(r3) : "r"(addr));
}

__device__ __forceinline__ void mma_bf16(float c[4], uint32_t a0, uint32_t a1,
                                         uint32_t a2, uint32_t a3,
                                         uint32_t b0, uint32_t b1) {
    asm volatile(
        "mma.sync.aligned.m16n8k16.row.col.f32.bf16.bf16.f32 "
        "{%0,%1,%2,%3}, {%4,%5,%6,%7}, {%8,%9}, {%0,%1,%2,%3};"
        : "+f"(c[0]), "+f"(c[1]), "+f"(c[2]), "+f"(c[3])
        : "r"(a0), "r"(a1), "r"(a2), "r"(a3), "r"(b0), "r"(b1));
}

// ---------------------------------------------------------------------------
// Split: fp32 -> bf16 hi + bf16 lo (x = hi + lo to ~2^-16 rel)
// ---------------------------------------------------------------------------
__global__ void split_k(const float* __restrict__ src, int which, int n4) {
    __nv_bfloat16 *hi, *lo;
    if      (which == 0) { hi = g_sh_hi; lo = g_sh_lo; }
    else if (which == 1) { hi = g_qi_hi; lo = g_qi_lo; }
    else if (which == 2) { hi = g_wk_hi; lo = g_wk_lo; }
    else                 { hi = g_wq_hi; lo = g_wq_lo; }
    int i = blockIdx.x * blockDim.x + threadIdx.x;
    if (i >= n4) return;
    float4 v = ((const float4*)src)[i];
    __nv_bfloat16 h0 = __float2bfloat16(v.x), h1 = __float2bfloat16(v.y);
    __nv_bfloat16 h2 = __float2bfloat16(v.z), h3 = __float2bfloat16(v.w);
    __nv_bfloat162 hh0; hh0.x = h0; hh0.y = h1;
    __nv_bfloat162 hh1; hh1.x = h2; hh1.y = h3;
    __nv_bfloat162 ll0, ll1;
    ll0.x = __float2bfloat16(v.x - __bfloat162float(h0));
    ll0.y = __float2bfloat16(v.y - __bfloat162float(h1));
    ll1.x = __float2bfloat16(v.z - __bfloat162float(h2));
    ll1.y = __float2bfloat16(v.w - __bfloat162float(h3));
    ((__nv_bfloat162*)hi)[i*2]   = hh0;
    ((__nv_bfloat162*)hi)[i*2+1] = hh1;
    ((__nv_bfloat162*)lo)[i*2]   = ll0;
    ((__nv_bfloat162*)lo)[i*2+1] = ll1;
}

// ---------------------------------------------------------------------------
// Projection GEMM (HMMA): C[128x128] = A @ W^T + bias over K = 3*768 (hi/lo
// split), bf16 in, fp32 accum. Output re-split to bf16 hi/lo.
// grid.x: 6 n-tiles; grid.y 0..127 K-proj, 128..129 Q-proj.
// smem: A0@0(16K) B0@16K A1@32K B1@48K = 64KB.
// ---------------------------------------------------------------------------
__global__ __launch_bounds__(256, 2)
void proj_tc(const float* __restrict__ bk, const float* __restrict__ bq)
{
    extern __shared__ char dsm[];
    const uint32_t sb = smem_u32(dsm);
    const int tid = threadIdx.x, wid = tid >> 5, lane = tid & 31;
    const int wm = wid & 3, wn = wid >> 2;

    const int by = blockIdx.y;
    const int n0 = blockIdx.x * 128;
    const __nv_bfloat16 *Ahi, *Alo, *Bhi, *Blo;
    __nv_bfloat16 *Ohi, *Olo;
    const float* bias;
    int m0;
    if (by < 128) { Ahi = g_sh_hi; Alo = g_sh_lo; Bhi = g_wk_hi; Blo = g_wk_lo;
                    Ohi = g_k_hi;  Olo = g_k_lo;  bias = bk; m0 = by * 128; }
    else          { Ahi = g_qi_hi; Alo = g_qi_lo; Bhi = g_wq_hi; Blo = g_wq_lo;
                    Ohi = g_qp_hi; Olo = g_qp_lo; bias = bq; m0 = (by - 128) * 128; }

    float c[2][8][4];
#pragma unroll
    for (int i = 0; i < 2; ++i)
#pragma unroll
        for (int j = 0; j < 8; ++j)
#pragma unroll
            for (int k = 0; k < 4; ++k) c[i][j][k] = 0.0f;

    // loader geometry: 1024 segs of 16B per 128x128B tile, 4 per thread
    auto issue = [&](int chunk, int buf) {
        const int t = chunk / 12, k0 = (chunk % 12) * 64;
        const __nv_bfloat16* As = (t == 1) ? Alo : Ahi;
        const __nv_bfloat16* Bs = (t == 2) ? Blo : Bhi;
        const uint32_t Ab = sb + (uint32_t)buf * 32768u;
        const uint32_t Bb = Ab + 16384u;
#pragma unroll
        for (int i = 0; i < 4; ++i) {
            const int seg = tid + 256 * i;
            const int row = seg >> 3, sg = seg & 7;
            const uint32_t off = (uint32_t)row * 128u + ((uint32_t)(sg * 16) ^ (uint32_t)((row & 7) << 4));
            cp16(Ab + off, As + (size_t)(m0 + row) * EMBED + k0 + sg * 8);
            cp16(Bb + off, Bs + (size_t)(n0 + row) * EMBED + k0 + sg * 8);
        }
        CP_COMMIT();
    };

    issue(0, 0);
    CP_WAIT0();
    __syncthreads();

    const int g  = lane >> 3;
    const int gr = ((g & 1) << 3) + (lane & 7);   // row-in-16 for A-style x4
    const int gk = (g >> 1) << 4;                 // k-byte select for A-style x4
    const int hr = ((g >> 1) << 3) + (lane & 7);  // row-in-16 for B-pair x4
    const int hk = (g & 1) << 4;                  // k-byte select for B-pair x4

#pragma unroll 1
    for (int ch = 0; ch < 36; ++ch) {
        const int b = ch & 1;
        if (ch + 1 < 36) issue(ch + 1, b ^ 1);

        const uint32_t Ab = sb + (uint32_t)b * 32768u;
        const uint32_t Bb = Ab + 16384u;
#pragma unroll
        for (int ks = 0; ks < 4; ++ks) {
            uint32_t a[2][4];
#pragma unroll
            for (int mt = 0; mt < 2; ++mt) {
                const int r = wm * 32 + mt * 16 + gr;
                const int kb = ks * 32 + gk;
                ldm_x4(a[mt][0], a[mt][1], a[mt][2], a[mt][3],
                       Ab + (uint32_t)r * 128u + (uint32_t)(kb ^ ((r & 7) << 4)));
            }
            uint32_t bf[8][2];
#pragma unroll
            for (int p = 0; p < 4; ++p) {
                const int r = wn * 64 + p * 16 + hr;
                const int kb = ks * 32 + hk;
                uint32_t r0, r1, r2, r3;
                ldm_x4(r0, r1, r2, r3,
                       Bb + (uint32_t)r * 128u + (uint32_t)(kb ^ ((r & 7) << 4)));
                bf[2*p][0] = r0;   bf[2*p][1] = r1;
                bf[2*p+1][0] = r2; bf[2*p+1][1] = r3;
            }
#pragma unroll
            for (int mt = 0; mt < 2; ++mt)
#pragma unroll
                for (int nt = 0; nt < 8; ++nt)
                    mma_bf16(c[mt][nt], a[mt][0], a[mt][1], a[mt][2], a[mt][3],
                             bf[nt][0], bf[nt][1]);
        }
        if (ch + 1 < 36) CP_WAIT0();
        __syncthreads();
    }

    // Epilogue: bias + hi/lo split, bf162 stores
#pragma unroll
    for (int mt = 0; mt < 2; ++mt) {
#pragma unroll
        for (int nt = 0; nt < 8; ++nt) {
            const int col = n0 + wn * 64 + nt * 8 + (lane & 3) * 2;
            const float bc0 = __ldg(bias + col), bc1 = __ldg(bias + col + 1);
#pragma unroll
            for (int h = 0; h < 2; ++h) {
                const int row = m0 + wm * 32 + mt * 16 + (lane >> 2) + h * 8;
                float x0 = c[mt][nt][2*h]   + bc0;
                float x1 = c[mt][nt][2*h+1] + bc1;
                __nv_bfloat16 h0 = __float2bfloat16(x0), h1 = __float2bfloat16(x1);
                __nv_bfloat162 hh; hh.x = h0; hh.y = h1;
                __nv_bfloat162 ll;
                ll.x = __float2bfloat16(x0 - __bfloat162float(h0));
                ll.y = __float2bfloat16(x1 - __bfloat162float(h1));
                *(__nv_bfloat162*)(Ohi + (size_t)row * EMBED + col) = hh;
                *(__nv_bfloat162*)(Olo + (size_t)row * EMBED + col) = ll;
            }
        }
    }
}

// ---------------------------------------------------------------------------
// Attention + fused MLP head (HMMA). Tile 64(b) x 128(n). Heads = 96 = 6
// k16-steps exactly (no padding). Per-head logits fold into hp[] via SCALE*W1
// at each 6th k-step; epilogue = GELU(erf) + W2.
// smem: A0@0(8K) B0@8K(16K) A1@24K B1@32K(16K) | w1@49152 mlp@49280
// ---------------------------------------------------------------------------
__global__ __launch_bounds__(256, 1)
void attn_tc(const float* __restrict__ W1, const float* __restrict__ b1,
             const float* __restrict__ W2, const float* __restrict__ b2,
             float* __restrict__ outp)
{
    extern __shared__ char dsm[];
    const uint32_t sb = smem_u32(dsm);
    float* s_w1 = (float*)(dsm + 49152);
    float* s_mi = (float*)(dsm + 49280);
    const int tid = threadIdx.x, wid = tid >> 5, lane = tid & 31;
    const int wm = wid & 1, wn = wid >> 1;

    if (tid < 32) s_w1[tid] = W1[tid] * SCALE;
    if (tid < 4)  { s_mi[tid] = b1[tid]; s_mi[4 + tid] = W2[tid]; }
    if (tid == 8) s_mi[8] = b2[0];

    const int m0 = blockIdx.x * 64;    // b tile (4)
    const int n0 = blockIdx.y * 128;   // n tile (128)

    float c[2][4][4];
    float hp[2][4][4][4];
#pragma unroll
    for (int i = 0; i < 2; ++i)
#pragma unroll
        for (int j = 0; j < 4; ++j)
#pragma unroll
            for (int k = 0; k < 4; ++k) {
                c[i][j][k] = 0.0f;
#pragma unroll
                for (int l = 0; l < 4; ++l) hp[i][j][k][l] = 0.0f;
            }

    auto issue = [&](int chunk, int buf) {
        const int t = chunk / 12, k0 = (chunk % 12) * 64;
        const __nv_bfloat16* As = (t == 1) ? g_qp_lo : g_qp_hi;
        const __nv_bfloat16* Bs = (t == 2) ? g_k_lo  : g_k_hi;
        const uint32_t Ab = sb + (uint32_t)buf * 24576u;
        const uint32_t Bb = Ab + 8192u;
#pragma unroll
        for (int i = 0; i < 2; ++i) {     // A: 512 segs
            const int seg = tid + 256 * i;
            const int row = seg >> 3, sg = seg & 7;
            const uint32_t off = (uint32_t)row * 128u + ((uint32_t)(sg * 16) ^ (uint32_t)((row & 7) << 4));
            cp16(Ab + off, As + (size_t)(m0 + row) * EMBED + k0 + sg * 8);
        }
#pragma unroll
        for (int i = 0; i < 4; ++i) {     // B: 1024 segs
            const int seg = tid + 256 * i;
            const int row = seg >> 3, sg = seg & 7;
            const uint32_t off = (uint32_t)row * 128u + ((uint32_t)(sg * 16) ^ (uint32_t)((row & 7) << 4));
            cp16(Bb + off, Bs + (size_t)(n0 + row) * EMBED + k0 + sg * 8);
        }
        CP_COMMIT();
    };

    issue(0, 0);
    CP_WAIT0();
    __syncthreads();

    const int g  = lane >> 3;
    const int gr = ((g & 1) << 3) + (lane & 7);
    const int gk = (g >> 1) << 4;
    const int hr = ((g >> 1) << 3) + (lane & 7);
    const int hk = (g & 1) << 4;

#pragma unroll 1
    for (int ch = 0; ch < 36; ++ch) {
        const int b = ch & 1;
        if (ch + 1 < 36) issue(ch + 1, b ^ 1);

        const uint32_t Ab = sb + (uint32_t)b * 24576u;
        const uint32_t Bb = Ab + 8192u;
        const int s_base = (ch % 12) * 4;   // k16-step index within term
#pragma unroll
        for (int ks = 0; ks < 4; ++ks) {
            uint32_t a[2][4];
#pragma unroll
            for (int mt = 0; mt < 2; ++mt) {
                const int r = wm * 32 + mt * 16 + gr;
                const int kb = ks * 32 + gk;
                ldm_x4(a[mt][0], a[mt][1], a[mt][2], a[mt][3],
                       Ab + (uint32_t)r * 128u + (uint32_t)(kb ^ ((r & 7) << 4)));
            }
            uint32_t bf[4][2];
#pragma unroll
            for (int p = 0; p < 2; ++p) {
                const int r = wn * 32 + p * 16 + hr;
                const int kb = ks * 32 + hk;
                uint32_t r0, r1, r2, r3;
                ldm_x4(r0, r1, r2, r3,
                       Bb + (uint32_t)r * 128u + (uint32_t)(kb ^ ((r & 7) << 4)));
                bf[2*p][0] = r0;   bf[2*p][1] = r1;
                bf[2*p+1][0] = r2; bf[2*p+1][1] = r3;
            }
#pragma unroll
            for (int mt = 0; mt < 2; ++mt)
#pragma unroll
                for (int nt = 0; nt < 4; ++nt)
                    mma_bf16(c[mt][nt], a[mt][0], a[mt][1], a[mt][2], a[mt][3],
                             bf[nt][0], bf[nt][1]);

            const int s = s_base + ks;
            if ((s % 6) == 5) {            // head boundary: fold into hp
                const int h = s / 6;
                const float w0 = s_w1[h],      w1v = s_w1[8 + h];
                const float w2v = s_w1[16 + h], w3 = s_w1[24 + h];
#pragma unroll
                for (int mt = 0; mt < 2; ++mt)
#pragma unroll
                    for (int nt = 0; nt < 4; ++nt)
#pragma unroll
                        for (int k = 0; k < 4; ++k) {
                            const float v = c[mt][nt][k];
                            hp[mt][nt][k][0] = fmaf(w0,  v, hp[mt][nt][k][0]);
                            hp[mt][nt][k][1] = fmaf(w1v, v, hp[mt][nt][k][1]);
                            hp[mt][nt][k][2] = fmaf(w2v, v, hp[mt][nt][k][2]);
                            hp[mt][nt][k][3] = fmaf(w3,  v, hp[mt][nt][k][3]);
                            c[mt][nt][k] = 0.0f;
                        }
            }
        }
        if (ch + 1 < 36) CP_WAIT0();
        __syncthreads();
    }

    // Epilogue: GELU(erf) + W2, float2 stores
    const float b10 = s_mi[0], b11 = s_mi[1], b12 = s_mi[2], b13 = s_mi[3];
    const float w20 = s_mi[4], w21 = s_mi[5], w22 = s_mi[6], w23 = s_mi[7];
    const float bb2 = s_mi[8];
    const float inv_sqrt2 = 0.70710678118654752f;
#pragma unroll
    for (int mt = 0; mt < 2; ++mt)
#pragma unroll
        for (int nt = 0; nt < 4; ++nt) {
            const int col = n0 + wn * 32 + nt * 8 + (lane & 3) * 2;
#pragma unroll
            for (int h = 0; h < 2; ++h) {
                const int row = m0 + wm * 32 + mt * 16 + (lane >> 2) + h * 8;
                float o[2];
#pragma unroll
                for (int e = 0; e < 2; ++e) {
                    const int k = 2 * h + e;
                    float x0 = hp[mt][nt][k][0] + b10;
                    float x1 = hp[mt][nt][k][1] + b11;
                    float x2 = hp[mt][nt][k][2] + b12;
                    float x3 = hp[mt][nt][k][3] + b13;
                    float g0 = 0.5f * x0 * (1.0f + erff(x0 * inv_sqrt2));
                    float g1 = 0.5f * x1 * (1.0f + erff(x1 * inv_sqrt2));
                    float g2 = 0.5f * x2 * (1.0f + erff(x2 * inv_sqrt2));
                    float g3 = 0.5f * x3 * (1.0f + erff(x3 * inv_sqrt2));
                    float s = bb2;
                    s = fmaf(w20, g0, s); s = fmaf(w21, g1, s);
                    s = fmaf(w22, g2, s); s = fmaf(w23, g3, s);
                    o[e] = s;
                }
                *(float2*)(outp + (size_t)row * NTOT + col) = make_float2(o[0], o[1]);
            }
        }
}

// ---------------------------------------------------------------------------
extern "C" void kernel_launch(void* const* d_in, const int* in_sizes, int n_in,
                              void* d_out, int out_size)
{
    const float* query  = (const float*)d_in[0];
    const float* search = (const float*)d_in[1];
    const float* Wq     = (const float*)d_in[2];
    const float* bq     = (const float*)d_in[3];
    const float* Wk     = (const float*)d_in[4];
    const float* bk     = (const float*)d_in[5];
    const float* W1     = (const float*)d_in[6];
    const float* b1     = (const float*)d_in[7];
    const float* W2     = (const float*)d_in[8];
    const float* b2     = (const float*)d_in[9];
    float* out = (float*)d_out;

    cudaFuncSetAttribute(proj_tc, cudaFuncAttributeMaxDynamicSharedMemorySize, 65536);
    cudaFuncSetAttribute(attn_tc, cudaFuncAttributeMaxDynamicSharedMemorySize, 49536);

    const int n4s = NTOT * EMBED / 4;
    const int n4q = BQ * EMBED / 4;
    const int n4w = EMBED * EMBED / 4;
    split_k<<<(n4s + 255) / 256, 256>>>(search, 0, n4s);
    split_k<<<(n4q + 255) / 256, 256>>>(query,  1, n4q);
    split_k<<<(n4w + 255) / 256, 256>>>(Wk,     2, n4w);
    split_k<<<(n4w + 255) / 256, 256>>>(Wq,     3, n4w);

    proj_tc<<<dim3(6, 130), 256, 65536>>>(bk, bq);
    attn_tc<<<dim3(4, 128), 256, 49536>>>(W1, b1, W2, b2, out);
}

// round 4
// speedup vs baseline: 2.3008x; 1.2723x over previous
#include <cuda_runtime.h>
#include <cuda_fp16.h>
#include <cstdint>
#include <math.h>

#define EMBED 768
#define BQ    256
#define NTOT  16384
#define SCALE 0.1020620726159657f   // 96^-0.5

// ---------------------------------------------------------------------------
// Device scratch (static globals — no runtime allocation)
// ---------------------------------------------------------------------------
__device__ __half g_sh_hi[NTOT*EMBED], g_sh_lo[NTOT*EMBED];     // search split
__device__ __half g_qi_hi[BQ*EMBED],   g_qi_lo[BQ*EMBED];       // query split
__device__ __half g_wk_hi[EMBED*EMBED], g_wk_lo[EMBED*EMBED];   // Wk split
__device__ __half g_wq_hi[EMBED*EMBED], g_wq_lo[EMBED*EMBED];   // Wq split
__device__ __half g_k_hi[NTOT*EMBED],  g_k_lo[NTOT*EMBED];      // projected K split
__device__ __half g_qp_hi[BQ*EMBED],   g_qp_lo[BQ*EMBED];       // projected Q split

// ---------------------------------------------------------------------------
// Helpers
// ---------------------------------------------------------------------------
__device__ __forceinline__ uint32_t smem_u32(const void* p) {
    uint32_t a;
    asm("{ .reg .u64 t; cvta.to.shared.u64 t, %1; cvt.u32.u64 %0, t; }"
        : "=r"(a) : "l"(p));
    return a;
}

__device__ __forceinline__ void cp16(uint32_t dst, const void* src) {
    asm volatile("cp.async.cg.shared.global [%0], [%1], 16;" :: "r"(dst), "l"(src));
}
#define CP_COMMIT() asm volatile("cp.async.commit_group;")
#define CP_WAIT0()  asm volatile("cp.async.wait_group 0;")

__device__ __forceinline__ void ldm_x4(uint32_t& r0, uint32_t& r1, uint32_t& r2,
                                       uint32_t& r3, uint32_t addr) {
    asm volatile("ldmatrix.sync.aligned.m8n8.x4.shared.b16 {%0,%1,%2,%3}, [%4];"
                 : "=r"(r0), "=r"(r1), "=r"(r2), "=r"(r3) : "r"(addr));
}

__device__ __forceinline__ void mma_f16(float c[4], uint32_t a0, uint32_t a1,
                                        uint32_t a2, uint32_t a3,
                                        uint32_t b0, uint32_t b1) {
    asm volatile(
        "mma.sync.aligned.m16n8k16.row.col.f32.f16.f16.f32 "
        "{%0,%1,%2,%3}, {%4,%5,%6,%7}, {%8,%9}, {%0,%1,%2,%3};"
        : "+f"(c[0]), "+f"(c[1]), "+f"(c[2]), "+f"(c[3])
        : "r"(a0), "r"(a1), "r"(a2), "r"(a3), "r"(b0), "r"(b1));
}

// ---------------------------------------------------------------------------
// Fused split: fp32 -> fp16 hi + fp16 lo for all four input tensors.
// Index ranges: [0,n4s) search | [n4s,+n4q) query | then Wk | then Wq.
// ---------------------------------------------------------------------------
#define N4S (NTOT*EMBED/4)
#define N4Q (BQ*EMBED/4)
#define N4W (EMBED*EMBED/4)

__global__ void split_all(const float* __restrict__ search,
                          const float* __restrict__ query,
                          const float* __restrict__ Wk,
                          const float* __restrict__ Wq) {
    int i = blockIdx.x * blockDim.x + threadIdx.x;
    const float* src;
    __half *hi, *lo;
    if (i < N4S)                      { src = search; hi = g_sh_hi; lo = g_sh_lo; }
    else if ((i -= N4S) < N4Q)        { src = query;  hi = g_qi_hi; lo = g_qi_lo; }
    else if ((i -= N4Q) < N4W)        { src = Wk;     hi = g_wk_hi; lo = g_wk_lo; }
    else if ((i -= N4W) < N4W)        { src = Wq;     hi = g_wq_hi; lo = g_wq_lo; }
    else return;
    float4 v = ((const float4*)src)[i];
    __half h0 = __float2half(v.x), h1 = __float2half(v.y);
    __half h2 = __float2half(v.z), h3 = __float2half(v.w);
    __half2 hh0 = __halves2half2(h0, h1), hh1 = __halves2half2(h2, h3);
    __half2 ll0 = __halves2half2(__float2half(v.x - __half2float(h0)),
                                 __float2half(v.y - __half2float(h1)));
    __half2 ll1 = __halves2half2(__float2half(v.z - __half2float(h2)),
                                 __float2half(v.w - __half2float(h3)));
    ((__half2*)hi)[i*2]   = hh0;
    ((__half2*)hi)[i*2+1] = hh1;
    ((__half2*)lo)[i*2]   = ll0;
    ((__half2*)lo)[i*2+1] = ll1;
}

// ---------------------------------------------------------------------------
// Projection GEMM (HMMA fp16, 2-term): C = A@W^T + bias over K = 2*768
// (hi*hi + lo_A*hi_B; dropped hi_A*lo_B ~ 2^-12). 128 threads, 4 warps 2x2,
// warp tile 64x64. CTA tile 128x128, k-chunk 64, double buffered.
// smem: A0@0(16K) B0@16K A1@32K B1@48K = 64KB. 2 CTA/SM.
// grid.x: 6 n-tiles; grid.y 0..127 K-proj, 128..129 Q-proj.
// ---------------------------------------------------------------------------
__global__ __launch_bounds__(128, 2)
void proj_tc(const float* __restrict__ bk, const float* __restrict__ bq)
{
    extern __shared__ char dsm[];
    const uint32_t sb = smem_u32(dsm);
    const int tid = threadIdx.x, wid = tid >> 5, lane = tid & 31;
    const int wm = wid & 1, wn = wid >> 1;

    const int by = blockIdx.y;
    const int n0 = blockIdx.x * 128;
    const __half *Ahi, *Alo, *Bhi;
    __half *Ohi, *Olo;
    const float* bias;
    int m0;
    if (by < 128) { Ahi = g_sh_hi; Alo = g_sh_lo; Bhi = g_wk_hi;
                    Ohi = g_k_hi;  Olo = g_k_lo;  bias = bk; m0 = by * 128; }
    else          { Ahi = g_qi_hi; Alo = g_qi_lo; Bhi = g_wq_hi;
                    Ohi = g_qp_hi; Olo = g_qp_lo; bias = bq; m0 = (by - 128) * 128; }

    float c[4][8][4];
#pragma unroll
    for (int i = 0; i < 4; ++i)
#pragma unroll
        for (int j = 0; j < 8; ++j)
#pragma unroll
            for (int k = 0; k < 4; ++k) c[i][j][k] = 0.0f;

    // loader: 1024 segs of 16B per 128x128B tile -> 8 per thread per matrix
    auto issue = [&](int chunk, int buf) {
        const int t = chunk / 12, k0 = (chunk % 12) * 64;
        const __half* As = t ? Alo : Ahi;
        const uint32_t Ab = sb + (uint32_t)buf * 32768u;
        const uint32_t Bb = Ab + 16384u;
#pragma unroll
        for (int i = 0; i < 8; ++i) {
            const int seg = tid + 128 * i;
            const int row = seg >> 3, sg = seg & 7;
            const uint32_t off = (uint32_t)row * 128u +
                                 ((uint32_t)(sg * 16) ^ (uint32_t)((row & 7) << 4));
            cp16(Ab + off, As  + (size_t)(m0 + row) * EMBED + k0 + sg * 8);
            cp16(Bb + off, Bhi + (size_t)(n0 + row) * EMBED + k0 + sg * 8);
        }
        CP_COMMIT();
    };

    issue(0, 0);
    CP_WAIT0();
    __syncthreads();

    const int g  = lane >> 3;
    const int gr = ((g & 1) << 3) + (lane & 7);   // A-frag row sel
    const int gk = (g >> 1) << 4;                 // A-frag k sel
    const int hr = ((g >> 1) << 3) + (lane & 7);  // B-frag row sel
    const int hk = (g & 1) << 4;                  // B-frag k sel

#pragma unroll 1
    for (int ch = 0; ch < 24; ++ch) {
        const int b = ch & 1;
        if (ch + 1 < 24) issue(ch + 1, b ^ 1);

        const uint32_t Ab = sb + (uint32_t)b * 32768u;
        const uint32_t Bb = Ab + 16384u;
#pragma unroll
        for (int ks = 0; ks < 4; ++ks) {
            uint32_t a[4][4];
#pragma unroll
            for (int mt = 0; mt < 4; ++mt) {
                const int r = wm * 64 + mt * 16 + gr;
                const int kb = ks * 32 + gk;
                ldm_x4(a[mt][0], a[mt][1], a[mt][2], a[mt][3],
                       Ab + (uint32_t)r * 128u + (uint32_t)(kb ^ ((r & 7) << 4)));
            }
            uint32_t bf[8][2];
#pragma unroll
            for (int p = 0; p < 4; ++p) {
                const int r = wn * 64 + p * 16 + hr;
                const int kb = ks * 32 + hk;
                uint32_t r0, r1, r2, r3;
                ldm_x4(r0, r1, r2, r3,
                       Bb + (uint32_t)r * 128u + (uint32_t)(kb ^ ((r & 7) << 4)));
                bf[2*p][0] = r0;   bf[2*p][1] = r1;
                bf[2*p+1][0] = r2; bf[2*p+1][1] = r3;
            }
#pragma unroll
            for (int mt = 0; mt < 4; ++mt)
#pragma unroll
                for (int nt = 0; nt < 8; ++nt)
                    mma_f16(c[mt][nt], a[mt][0], a[mt][1], a[mt][2], a[mt][3],
                            bf[nt][0], bf[nt][1]);
        }
        if (ch + 1 < 24) CP_WAIT0();
        __syncthreads();
    }

    // Epilogue: bias + fp16 hi/lo split
#pragma unroll
    for (int mt = 0; mt < 4; ++mt) {
#pragma unroll
        for (int nt = 0; nt < 8; ++nt) {
            const int col = n0 + wn * 64 + nt * 8 + (lane & 3) * 2;
            const float bc0 = __ldg(bias + col), bc1 = __ldg(bias + col + 1);
#pragma unroll
            for (int h = 0; h < 2; ++h) {
                const int row = m0 + wm * 64 + mt * 16 + (lane >> 2) + h * 8;
                float x0 = c[mt][nt][2*h]   + bc0;
                float x1 = c[mt][nt][2*h+1] + bc1;
                __half h0 = __float2half(x0), h1 = __float2half(x1);
                __half2 hh = __halves2half2(h0, h1);
                __half2 ll = __halves2half2(__float2half(x0 - __half2float(h0)),
                                            __float2half(x1 - __half2float(h1)));
                *(__half2*)(Ohi + (size_t)row * EMBED + col) = hh;
                *(__half2*)(Olo + (size_t)row * EMBED + col) = ll;
            }
        }
    }
}

// ---------------------------------------------------------------------------
// Attention + fused MLP head (HMMA fp16, 3-term). Tile 64(b) x 128(n).
// Heads = 96 = 6 k16-steps exactly. Per-head logits fold into hp[] via
// SCALE*W1 at each 6th k-step; epilogue = GELU(erf) + W2.
// smem: A0@0(8K) B0@8K(16K) A1@24K B1@32K(16K) | w1@49152 mlp@49280
// ---------------------------------------------------------------------------
__global__ __launch_bounds__(256, 1)
void attn_tc(const float* __restrict__ W1, const float* __restrict__ b1,
             const float* __restrict__ W2, const float* __restrict__ b2,
             float* __restrict__ outp)
{
    extern __shared__ char dsm[];
    const uint32_t sb = smem_u32(dsm);
    float* s_w1 = (float*)(dsm + 49152);
    float* s_mi = (float*)(dsm + 49280);
    const int tid = threadIdx.x, wid = tid >> 5, lane = tid & 31;
    const int wm = wid & 1, wn = wid >> 1;

    if (tid < 32) s_w1[tid] = W1[tid] * SCALE;
    if (tid < 4)  { s_mi[tid] = b1[tid]; s_mi[4 + tid] = W2[tid]; }
    if (tid == 8) s_mi[8] = b2[0];

    const int m0 = blockIdx.x * 64;    // b tile (4)
    const int n0 = blockIdx.y * 128;   // n tile (128)

    float c[2][4][4];
    float hp[2][4][4][4];
#pragma unroll
    for (int i = 0; i < 2; ++i)
#pragma unroll
        for (int j = 0; j < 4; ++j)
#pragma unroll
            for (int k = 0; k < 4; ++k) {
                c[i][j][k] = 0.0f;
#pragma unroll
                for (int l = 0; l < 4; ++l) hp[i][j][k][l] = 0.0f;
            }

    auto issue = [&](int chunk, int buf) {
        const int t = chunk / 12, k0 = (chunk % 12) * 64;
        const __half* As = (t == 1) ? g_qp_lo : g_qp_hi;
        const __half* Bs = (t == 2) ? g_k_lo  : g_k_hi;
        const uint32_t Ab = sb + (uint32_t)buf * 24576u;
        const uint32_t Bb = Ab + 8192u;
#pragma unroll
        for (int i = 0; i < 2; ++i) {     // A: 512 segs
            const int seg = tid + 256 * i;
            const int row = seg >> 3, sg = seg & 7;
            const uint32_t off = (uint32_t)row * 128u +
                                 ((uint32_t)(sg * 16) ^ (uint32_t)((row & 7) << 4));
            cp16(Ab + off, As + (size_t)(m0 + row) * EMBED + k0 + sg * 8);
        }
#pragma unroll
        for (int i = 0; i < 4; ++i) {     // B: 1024 segs
            const int seg = tid + 256 * i;
            const int row = seg >> 3, sg = seg & 7;
            const uint32_t off = (uint32_t)row * 128u +
                                 ((uint32_t)(sg * 16) ^ (uint32_t)((row & 7) << 4));
            cp16(Bb + off, Bs + (size_t)(n0 + row) * EMBED + k0 + sg * 8);
        }
        CP_COMMIT();
    };

    issue(0, 0);
    CP_WAIT0();
    __syncthreads();

    const int g  = lane >> 3;
    const int gr = ((g & 1) << 3) + (lane & 7);
    const int gk = (g >> 1) << 4;
    const int hr = ((g >> 1) << 3) + (lane & 7);
    const int hk = (g & 1) << 4;

#pragma unroll 1
    for (int ch = 0; ch < 36; ++ch) {
        const int b = ch & 1;
        if (ch + 1 < 36) issue(ch + 1, b ^ 1);

        const uint32_t Ab = sb + (uint32_t)b * 24576u;
        const uint32_t Bb = Ab + 8192u;
        const int s_base = (ch % 12) * 4;
#pragma unroll
        for (int ks = 0; ks < 4; ++ks) {
            uint32_t a[2][4];
#pragma unroll
            for (int mt = 0; mt < 2; ++mt) {
                const int r = wm * 32 + mt * 16 + gr;
                const int kb = ks * 32 + gk;
                ldm_x4(a[mt][0], a[mt][1], a[mt][2], a[mt][3],
                       Ab + (uint32_t)r * 128u + (uint32_t)(kb ^ ((r & 7) << 4)));
            }
            uint32_t bf[4][2];
#pragma unroll
            for (int p = 0; p < 2; ++p) {
                const int r = wn * 32 + p * 16 + hr;
                const int kb = ks * 32 + hk;
                uint32_t r0, r1, r2, r3;
                ldm_x4(r0, r1, r2, r3,
                       Bb + (uint32_t)r * 128u + (uint32_t)(kb ^ ((r & 7) << 4)));
                bf[2*p][0] = r0;   bf[2*p][1] = r1;
                bf[2*p+1][0] = r2; bf[2*p+1][1] = r3;
            }
#pragma unroll
            for (int mt = 0; mt < 2; ++mt)
#pragma unroll
                for (int nt = 0; nt < 4; ++nt)
                    mma_f16(c[mt][nt], a[mt][0], a[mt][1], a[mt][2], a[mt][3],
                            bf[nt][0], bf[nt][1]);

            const int s = s_base + ks;
            if ((s % 6) == 5) {            // head boundary: fold into hp
                const int h = s / 6;
                const float w0 = s_w1[h],       w1v = s_w1[8 + h];
                const float w2v = s_w1[16 + h], w3  = s_w1[24 + h];
#pragma unroll
                for (int mt = 0; mt < 2; ++mt)
#pragma unroll
                    for (int nt = 0; nt < 4; ++nt)
#pragma unroll
                        for (int k = 0; k < 4; ++k) {
                            const float v = c[mt][nt][k];
                            hp[mt][nt][k][0] = fmaf(w0,  v, hp[mt][nt][k][0]);
                            hp[mt][nt][k][1] = fmaf(w1v, v, hp[mt][nt][k][1]);
                            hp[mt][nt][k][2] = fmaf(w2v, v, hp[mt][nt][k][2]);
                            hp[mt][nt][k][3] = fmaf(w3,  v, hp[mt][nt][k][3]);
                            c[mt][nt][k] = 0.0f;
                        }
            }
        }
        if (ch + 1 < 36) CP_WAIT0();
        __syncthreads();
    }

    // Epilogue: GELU(erf) + W2, float2 stores
    const float b10 = s_mi[0], b11 = s_mi[1], b12 = s_mi[2], b13 = s_mi[3];
    const float w20 = s_mi[4], w21 = s_mi[5], w22 = s_mi[6], w23 = s_mi[7];
    const float bb2 = s_mi[8];
    const float inv_sqrt2 = 0.70710678118654752f;
#pragma unroll
    for (int mt = 0; mt < 2; ++mt)
#pragma unroll
        for (int nt = 0; nt < 4; ++nt) {
            const int col = n0 + wn * 32 + nt * 8 + (lane & 3) * 2;
#pragma unroll
            for (int h = 0; h < 2; ++h) {
                const int row = m0 + wm * 32 + mt * 16 + (lane >> 2) + h * 8;
                float o[2];
#pragma unroll
                for (int e = 0; e < 2; ++e) {
                    const int k = 2 * h + e;
                    float x0 = hp[mt][nt][k][0] + b10;
                    float x1 = hp[mt][nt][k][1] + b11;
                    float x2 = hp[mt][nt][k][2] + b12;
                    float x3 = hp[mt][nt][k][3] + b13;
                    float g0 = 0.5f * x0 * (1.0f + erff(x0 * inv_sqrt2));
                    float g1 = 0.5f * x1 * (1.0f + erff(x1 * inv_sqrt2));
                    float g2 = 0.5f * x2 * (1.0f + erff(x2 * inv_sqrt2));
                    float g3 = 0.5f * x3 * (1.0f + erff(x3 * inv_sqrt2));
                    float s = bb2;
                    s = fmaf(w20, g0, s); s = fmaf(w21, g1, s);
                    s = fmaf(w22, g2, s); s = fmaf(w23, g3, s);
                    o[e] = s;
                }
                *(float2*)(outp + (size_t)row * NTOT + col) = make_float2(o[0], o[1]);
            }
        }
}

// ---------------------------------------------------------------------------
extern "C" void kernel_launch(void* const* d_in, const int* in_sizes, int n_in,
                              void* d_out, int out_size)
{
    const float* query  = (const float*)d_in[0];
    const float* search = (const float*)d_in[1];
    const float* Wq     = (const float*)d_in[2];
    const float* bq     = (const float*)d_in[3];
    const float* Wk     = (const float*)d_in[4];
    const float* bk     = (const float*)d_in[5];
    const float* W1     = (const float*)d_in[6];
    const float* b1     = (const float*)d_in[7];
    const float* W2     = (const float*)d_in[8];
    const float* b2     = (const float*)d_in[9];
    float* out = (float*)d_out;

    cudaFuncSetAttribute(proj_tc, cudaFuncAttributeMaxDynamicSharedMemorySize, 65536);
    cudaFuncSetAttribute(attn_tc, cudaFuncAttributeMaxDynamicSharedMemorySize, 49536);

    const int total4 = N4S + N4Q + 2 * N4W;
    split_all<<<(total4 + 255) / 256, 256>>>(search, query, Wk, Wq);

    proj_tc<<<dim3(6, 130), 128, 65536>>>(bk, bq);
    attn_tc<<<dim3(4, 128), 256, 49536>>>(W1, b1, W2, b2, out);
}

// round 5
// speedup vs baseline: 3.1075x; 1.3506x over previous
#include <cuda_runtime.h>
#include <cuda_fp16.h>
#include <cstdint>
#include <math.h>

#define EMBED 768
#define BQ    256
#define NTOT  16384
#define SCALE 0.1020620726159657f   // 96^-0.5

// ---------------------------------------------------------------------------
// Device scratch (static globals — no runtime allocation)
// ---------------------------------------------------------------------------
__device__ __half g_sh_hi[NTOT*EMBED], g_sh_lo[NTOT*EMBED];     // search split
__device__ __half g_qi_hi[BQ*EMBED],   g_qi_lo[BQ*EMBED];       // query split
__device__ __half g_wk_hi[EMBED*EMBED];                         // Wk hi (lo unused)
__device__ __half g_wq_hi[EMBED*EMBED];                         // Wq hi (lo unused)
__device__ __half g_k_hi[NTOT*EMBED];                           // projected K hi (lo unused)
__device__ __half g_qp_hi[BQ*EMBED],   g_qp_lo[BQ*EMBED];       // projected Q split

// ---------------------------------------------------------------------------
// Helpers
// ---------------------------------------------------------------------------
__device__ __forceinline__ uint32_t smem_u32(const void* p) {
    uint32_t a;
    asm("{ .reg .u64 t; cvta.to.shared.u64 t, %1; cvt.u32.u64 %0, t; }"
        : "=r"(a) : "l"(p));
    return a;
}

__device__ __forceinline__ void cp16(uint32_t dst, const void* src) {
    asm volatile("cp.async.cg.shared.global [%0], [%1], 16;" :: "r"(dst), "l"(src));
}
#define CP_COMMIT() asm volatile("cp.async.commit_group;")
#define CP_WAIT0()  asm volatile("cp.async.wait_group 0;")

__device__ __forceinline__ void ldm_x4(uint32_t& r0, uint32_t& r1, uint32_t& r2,
                                       uint32_t& r3, uint32_t addr) {
    asm volatile("ldmatrix.sync.aligned.m8n8.x4.shared.b16 {%0,%1,%2,%3}, [%4];"
                 : "=r"(r0), "=r"(r1), "=r"(r2), "=r"(r3) : "r"(addr));
}

__device__ __forceinline__ void mma_f16(float c[4], uint32_t a0, uint32_t a1,
                                        uint32_t a2, uint32_t a3,
                                        uint32_t b0, uint32_t b1) {
    asm volatile(
        "mma.sync.aligned.m16n8k16.row.col.f32.f16.f16.f32 "
        "{%0,%1,%2,%3}, {%4,%5,%6,%7}, {%8,%9}, {%0,%1,%2,%3};"
        : "+f"(c[0]), "+f"(c[1]), "+f"(c[2]), "+f"(c[3])
        : "r"(a0), "r"(a1), "r"(a2), "r"(a3), "r"(b0), "r"(b1));
}

// ---------------------------------------------------------------------------
// Fused split: fp32 -> fp16 hi (+ lo where needed).
// search/query: hi+lo.  Wk/Wq: hi only (lo term never consumed).
// ---------------------------------------------------------------------------
#define N4S (NTOT*EMBED/4)
#define N4Q (BQ*EMBED/4)
#define N4W (EMBED*EMBED/4)

__global__ void split_all(const float* __restrict__ search,
                          const float* __restrict__ query,
                          const float* __restrict__ Wk,
                          const float* __restrict__ Wq) {
    int i = blockIdx.x * blockDim.x + threadIdx.x;
    const float* src;
    __half *hi, *lo = nullptr;
    if (i < N4S)                      { src = search; hi = g_sh_hi; lo = g_sh_lo; }
    else if ((i -= N4S) < N4Q)        { src = query;  hi = g_qi_hi; lo = g_qi_lo; }
    else if ((i -= N4Q) < N4W)        { src = Wk;     hi = g_wk_hi; }
    else if ((i -= N4W) < N4W)        { src = Wq;     hi = g_wq_hi; }
    else return;
    float4 v = ((const float4*)src)[i];
    __half h0 = __float2half(v.x), h1 = __float2half(v.y);
    __half h2 = __float2half(v.z), h3 = __float2half(v.w);
    ((__half2*)hi)[i*2]   = __halves2half2(h0, h1);
    ((__half2*)hi)[i*2+1] = __halves2half2(h2, h3);
    if (lo) {
        ((__half2*)lo)[i*2]   = __halves2half2(__float2half(v.x - __half2float(h0)),
                                               __float2half(v.y - __half2float(h1)));
        ((__half2*)lo)[i*2+1] = __halves2half2(__float2half(v.z - __half2float(h2)),
                                               __float2half(v.w - __half2float(h3)));
    }
}

// ---------------------------------------------------------------------------
// Projection GEMM (HMMA fp16, 2-term, both terms per chunk):
// C = (A_hi + A_lo) @ W_hi^T + bias, K = 768 in 12 chunks of 64.
// Per chunk smem: A_hi(16K) A_lo(16K) B(16K) = 48K, double buffered = 96K.
// B fragments loaded once per k-step, reused by both A terms.
// 128 threads, warps 2x2, warp tile 64x64. 2 CTA/SM.
// grid.x: 6 n-tiles; grid.y 0..127 K-proj, 128..129 Q-proj.
// ---------------------------------------------------------------------------
__global__ __launch_bounds__(128, 2)
void proj_tc(const float* __restrict__ bk, const float* __restrict__ bq)
{
    extern __shared__ char dsm[];
    const uint32_t sb = smem_u32(dsm);
    const int tid = threadIdx.x, wid = tid >> 5, lane = tid & 31;
    const int wm = wid & 1, wn = wid >> 1;

    const int by = blockIdx.y;
    const int n0 = blockIdx.x * 128;
    const __half *Ahi, *Alo, *Bhi;
    __half *Ohi, *Olo = nullptr;
    const float* bias;
    int m0;
    bool wlo;
    if (by < 128) { Ahi = g_sh_hi; Alo = g_sh_lo; Bhi = g_wk_hi;
                    Ohi = g_k_hi;  bias = bk; m0 = by * 128; wlo = false; }
    else          { Ahi = g_qi_hi; Alo = g_qi_lo; Bhi = g_wq_hi;
                    Ohi = g_qp_hi; Olo = g_qp_lo; bias = bq;
                    m0 = (by - 128) * 128; wlo = true; }

    float c[4][8][4];
#pragma unroll
    for (int i = 0; i < 4; ++i)
#pragma unroll
        for (int j = 0; j < 8; ++j)
#pragma unroll
            for (int k = 0; k < 4; ++k) c[i][j][k] = 0.0f;

    // loader: 3 tiles (Ahi, Alo, B) of 1024 segs -> 8 per thread per tile
    auto issue = [&](int chunk, int buf) {
        const int k0 = chunk * 64;
        const uint32_t base = sb + (uint32_t)buf * 49152u;
#pragma unroll
        for (int i = 0; i < 8; ++i) {
            const int seg = tid + 128 * i;
            const int row = seg >> 3, sg = seg & 7;
            const uint32_t off = (uint32_t)row * 128u +
                                 ((uint32_t)(sg * 16) ^ (uint32_t)((row & 7) << 4));
            cp16(base + off,          Ahi + (size_t)(m0 + row) * EMBED + k0 + sg * 8);
            cp16(base + 16384u + off, Alo + (size_t)(m0 + row) * EMBED + k0 + sg * 8);
            cp16(base + 32768u + off, Bhi + (size_t)(n0 + row) * EMBED + k0 + sg * 8);
        }
        CP_COMMIT();
    };

    issue(0, 0);
    CP_WAIT0();
    __syncthreads();

    const int g  = lane >> 3;
    const int gr = ((g & 1) << 3) + (lane & 7);   // A-frag row sel
    const int gk = (g >> 1) << 4;                 // A-frag k sel
    const int hr = ((g >> 1) << 3) + (lane & 7);  // B-frag row sel
    const int hk = (g & 1) << 4;                  // B-frag k sel

#pragma unroll 1
    for (int ch = 0; ch < 12; ++ch) {
        const int b = ch & 1;
        if (ch + 1 < 12) issue(ch + 1, b ^ 1);

        const uint32_t Ab = sb + (uint32_t)b * 49152u;
        const uint32_t Bb = Ab + 32768u;
#pragma unroll
        for (int ks = 0; ks < 4; ++ks) {
            uint32_t bf[8][2];
#pragma unroll
            for (int p = 0; p < 4; ++p) {
                const int r = wn * 64 + p * 16 + hr;
                const int kb = ks * 32 + hk;
                uint32_t r0, r1, r2, r3;
                ldm_x4(r0, r1, r2, r3,
                       Bb + (uint32_t)r * 128u + (uint32_t)(kb ^ ((r & 7) << 4)));
                bf[2*p][0] = r0;   bf[2*p][1] = r1;
                bf[2*p+1][0] = r2; bf[2*p+1][1] = r3;
            }
#pragma unroll
            for (int t = 0; t < 2; ++t) {
                const uint32_t At = Ab + (uint32_t)t * 16384u;
                uint32_t a[4][4];
#pragma unroll
                for (int mt = 0; mt < 4; ++mt) {
                    const int r = wm * 64 + mt * 16 + gr;
                    const int kb = ks * 32 + gk;
                    ldm_x4(a[mt][0], a[mt][1], a[mt][2], a[mt][3],
                           At + (uint32_t)r * 128u + (uint32_t)(kb ^ ((r & 7) << 4)));
                }
#pragma unroll
                for (int mt = 0; mt < 4; ++mt)
#pragma unroll
                    for (int nt = 0; nt < 8; ++nt)
                        mma_f16(c[mt][nt], a[mt][0], a[mt][1], a[mt][2], a[mt][3],
                                bf[nt][0], bf[nt][1]);
            }
        }
        if (ch + 1 < 12) CP_WAIT0();
        __syncthreads();
    }

    // Epilogue: bias + fp16 split; lo written only for Q-proj.
#pragma unroll
    for (int mt = 0; mt < 4; ++mt) {
#pragma unroll
        for (int nt = 0; nt < 8; ++nt) {
            const int col = n0 + wn * 64 + nt * 8 + (lane & 3) * 2;
            const float bc0 = __ldg(bias + col), bc1 = __ldg(bias + col + 1);
#pragma unroll
            for (int h = 0; h < 2; ++h) {
                const int row = m0 + wm * 64 + mt * 16 + (lane >> 2) + h * 8;
                float x0 = c[mt][nt][2*h]   + bc0;
                float x1 = c[mt][nt][2*h+1] + bc1;
                __half h0 = __float2half(x0), h1 = __float2half(x1);
                *(__half2*)(Ohi + (size_t)row * EMBED + col) = __halves2half2(h0, h1);
                if (wlo) {
                    __half2 ll = __halves2half2(__float2half(x0 - __half2float(h0)),
                                                __float2half(x1 - __half2float(h1)));
                    *(__half2*)(Olo + (size_t)row * EMBED + col) = ll;
                }
            }
        }
    }
}

// ---------------------------------------------------------------------------
// Attention + fused MLP head (HMMA fp16, 2-term, both terms per chunk):
// logits = (Q_hi + Q_lo) @ K_hi^T. Tile 64(b) x 128(n), 12 chunks of 64.
// Heads = 96 = 6 k16-steps; fold into hp[] via SCALE*W1 at s%6==5.
// smem per buffer: Qhi 8K | Qlo 8K | K 16K = 32K, x2 = 64K; params @65536.
// ---------------------------------------------------------------------------
__global__ __launch_bounds__(256, 1)
void attn_tc(const float* __restrict__ W1, const float* __restrict__ b1,
             const float* __restrict__ W2, const float* __restrict__ b2,
             float* __restrict__ outp)
{
    extern __shared__ char dsm[];
    const uint32_t sb = smem_u32(dsm);
    float* s_w1 = (float*)(dsm + 65536);
    float* s_mi = (float*)(dsm + 65664);
    const int tid = threadIdx.x, wid = tid >> 5, lane = tid & 31;
    const int wm = wid & 1, wn = wid >> 1;

    if (tid < 32) s_w1[tid] = W1[tid] * SCALE;
    if (tid < 4)  { s_mi[tid] = b1[tid]; s_mi[4 + tid] = W2[tid]; }
    if (tid == 8) s_mi[8] = b2[0];

    const int m0 = blockIdx.x * 64;    // b tile (4)
    const int n0 = blockIdx.y * 128;   // n tile (128)

    float c[2][4][4];
    float hp[2][4][4][4];
#pragma unroll
    for (int i = 0; i < 2; ++i)
#pragma unroll
        for (int j = 0; j < 4; ++j)
#pragma unroll
            for (int k = 0; k < 4; ++k) {
                c[i][j][k] = 0.0f;
#pragma unroll
                for (int l = 0; l < 4; ++l) hp[i][j][k][l] = 0.0f;
            }

    auto issue = [&](int chunk, int buf) {
        const int k0 = chunk * 64;
        const uint32_t base = sb + (uint32_t)buf * 32768u;
#pragma unroll
        for (int i = 0; i < 2; ++i) {     // Qhi + Qlo: 512 segs each
            const int seg = tid + 256 * i;
            const int row = seg >> 3, sg = seg & 7;
            const uint32_t off = (uint32_t)row * 128u +
                                 ((uint32_t)(sg * 16) ^ (uint32_t)((row & 7) << 4));
            cp16(base + off,         g_qp_hi + (size_t)(m0 + row) * EMBED + k0 + sg * 8);
            cp16(base + 8192u + off, g_qp_lo + (size_t)(m0 + row) * EMBED + k0 + sg * 8);
        }
#pragma unroll
        for (int i = 0; i < 4; ++i) {     // K: 1024 segs
            const int seg = tid + 256 * i;
            const int row = seg >> 3, sg = seg & 7;
            const uint32_t off = (uint32_t)row * 128u +
                                 ((uint32_t)(sg * 16) ^ (uint32_t)((row & 7) << 4));
            cp16(base + 16384u + off, g_k_hi + (size_t)(n0 + row) * EMBED + k0 + sg * 8);
        }
        CP_COMMIT();
    };

    issue(0, 0);
    CP_WAIT0();
    __syncthreads();

    const int g  = lane >> 3;
    const int gr = ((g & 1) << 3) + (lane & 7);
    const int gk = (g >> 1) << 4;
    const int hr = ((g >> 1) << 3) + (lane & 7);
    const int hk = (g & 1) << 4;

#pragma unroll 1
    for (int ch = 0; ch < 12; ++ch) {
        const int b = ch & 1;
        if (ch + 1 < 12) issue(ch + 1, b ^ 1);

        const uint32_t Ab = sb + (uint32_t)b * 32768u;
        const uint32_t Bb = Ab + 16384u;
#pragma unroll
        for (int ks = 0; ks < 4; ++ks) {
            uint32_t bf[4][2];
#pragma unroll
            for (int p = 0; p < 2; ++p) {
                const int r = wn * 32 + p * 16 + hr;
                const int kb = ks * 32 + hk;
                uint32_t r0, r1, r2, r3;
                ldm_x4(r0, r1, r2, r3,
                       Bb + (uint32_t)r * 128u + (uint32_t)(kb ^ ((r & 7) << 4)));
                bf[2*p][0] = r0;   bf[2*p][1] = r1;
                bf[2*p+1][0] = r2; bf[2*p+1][1] = r3;
            }
#pragma unroll
            for (int t = 0; t < 2; ++t) {
                const uint32_t At = Ab + (uint32_t)t * 8192u;
                uint32_t a[2][4];
#pragma unroll
                for (int mt = 0; mt < 2; ++mt) {
                    const int r = wm * 32 + mt * 16 + gr;
                    const int kb = ks * 32 + gk;
                    ldm_x4(a[mt][0], a[mt][1], a[mt][2], a[mt][3],
                           At + (uint32_t)r * 128u + (uint32_t)(kb ^ ((r & 7) << 4)));
                }
#pragma unroll
                for (int mt = 0; mt < 2; ++mt)
#pragma unroll
                    for (int nt = 0; nt < 4; ++nt)
                        mma_f16(c[mt][nt], a[mt][0], a[mt][1], a[mt][2], a[mt][3],
                                bf[nt][0], bf[nt][1]);
            }

            const int s = ch * 4 + ks;
            if ((s % 6) == 5) {            // head boundary: fold into hp
                const int h = s / 6;
                const float w0 = s_w1[h],       w1v = s_w1[8 + h];
                const float w2v = s_w1[16 + h], w3  = s_w1[24 + h];
#pragma unroll
                for (int mt = 0; mt < 2; ++mt)
#pragma unroll
                    for (int nt = 0; nt < 4; ++nt)
#pragma unroll
                        for (int k = 0; k < 4; ++k) {
                            const float v = c[mt][nt][k];
                            hp[mt][nt][k][0] = fmaf(w0,  v, hp[mt][nt][k][0]);
                            hp[mt][nt][k][1] = fmaf(w1v, v, hp[mt][nt][k][1]);
                            hp[mt][nt][k][2] = fmaf(w2v, v, hp[mt][nt][k][2]);
                            hp[mt][nt][k][3] = fmaf(w3,  v, hp[mt][nt][k][3]);
                            c[mt][nt][k] = 0.0f;
                        }
            }
        }
        if (ch + 1 < 12) CP_WAIT0();
        __syncthreads();
    }

    // Epilogue: GELU(erf) + W2, float2 stores
    const float b10 = s_mi[0], b11 = s_mi[1], b12 = s_mi[2], b13 = s_mi[3];
    const float w20 = s_mi[4], w21 = s_mi[5], w22 = s_mi[6], w23 = s_mi[7];
    const float bb2 = s_mi[8];
    const float inv_sqrt2 = 0.70710678118654752f;
#pragma unroll
    for (int mt = 0; mt < 2; ++mt)
#pragma unroll
        for (int nt = 0; nt < 4; ++nt) {
            const int col = n0 + wn * 32 + nt * 8 + (lane & 3) * 2;
#pragma unroll
            for (int h = 0; h < 2; ++h) {
                const int row = m0 + wm * 32 + mt * 16 + (lane >> 2) + h * 8;
                float o[2];
#pragma unroll
                for (int e = 0; e < 2; ++e) {
                    const int k = 2 * h + e;
                    float x0 = hp[mt][nt][k][0] + b10;
                    float x1 = hp[mt][nt][k][1] + b11;
                    float x2 = hp[mt][nt][k][2] + b12;
                    float x3 = hp[mt][nt][k][3] + b13;
                    float g0 = 0.5f * x0 * (1.0f + erff(x0 * inv_sqrt2));
                    float g1 = 0.5f * x1 * (1.0f + erff(x1 * inv_sqrt2));
                    float g2 = 0.5f * x2 * (1.0f + erff(x2 * inv_sqrt2));
                    float g3 = 0.5f * x3 * (1.0f + erff(x3 * inv_sqrt2));
                    float s = bb2;
                    s = fmaf(w20, g0, s); s = fmaf(w21, g1, s);
                    s = fmaf(w22, g2, s); s = fmaf(w23, g3, s);
                    o[e] = s;
                }
                *(float2*)(outp + (size_t)row * NTOT + col) = make_float2(o[0], o[1]);
            }
        }
}

// ---------------------------------------------------------------------------
extern "C" void kernel_launch(void* const* d_in, const int* in_sizes, int n_in,
                              void* d_out, int out_size)
{
    const float* query  = (const float*)d_in[0];
    const float* search = (const float*)d_in[1];
    const float* Wq     = (const float*)d_in[2];
    const float* bq     = (const float*)d_in[3];
    const float* Wk     = (const float*)d_in[4];
    const float* bk     = (const float*)d_in[5];
    const float* W1     = (const float*)d_in[6];
    const float* b1     = (const float*)d_in[7];
    const float* W2     = (const float*)d_in[8];
    const float* b2     = (const float*)d_in[9];
    float* out = (float*)d_out;

    cudaFuncSetAttribute(proj_tc, cudaFuncAttributeMaxDynamicSharedMemorySize, 98304);
    cudaFuncSetAttribute(attn_tc, cudaFuncAttributeMaxDynamicSharedMemorySize, 65792);

    const int total4 = N4S + N4Q + 2 * N4W;
    split_all<<<(total4 + 255) / 256, 256>>>(search, query, Wk, Wq);

    proj_tc<<<dim3(6, 130), 128, 98304>>>(bk, bq);
    attn_tc<<<dim3(4, 128), 256, 65792>>>(W1, b1, W2, b2, out);
}

// round 6
// speedup vs baseline: 3.6357x; 1.1700x over previous
#include <cuda_runtime.h>
#include <cuda_fp16.h>
#include <cstdint>
#include <math.h>

#define EMBED 768
#define BQ    256
#define NTOT  16384
#define SCALE 0.1020620726159657f   // 96^-0.5

// ---------------------------------------------------------------------------
// Device scratch (static globals — no runtime allocation)
// ---------------------------------------------------------------------------
__device__ __half g_sh_hi[NTOT*EMBED];                          // search hi (lo dropped)
__device__ __half g_qi_hi[BQ*EMBED],   g_qi_lo[BQ*EMBED];       // query split
__device__ __half g_wk_hi[EMBED*EMBED];                         // Wk hi
__device__ __half g_wq_hi[EMBED*EMBED];                         // Wq hi
__device__ __half g_k_hi[NTOT*EMBED];                           // projected K hi
__device__ __half g_qp_hi[BQ*EMBED],   g_qp_lo[BQ*EMBED];       // projected Q split

// ---------------------------------------------------------------------------
// Helpers
// ---------------------------------------------------------------------------
__device__ __forceinline__ uint32_t smem_u32(const void* p) {
    uint32_t a;
    asm("{ .reg .u64 t; cvta.to.shared.u64 t, %1; cvt.u32.u64 %0, t; }"
        : "=r"(a) : "l"(p));
    return a;
}

__device__ __forceinline__ void cp16(uint32_t dst, const void* src) {
    asm volatile("cp.async.cg.shared.global [%0], [%1], 16;" :: "r"(dst), "l"(src));
}
#define CP_COMMIT() asm volatile("cp.async.commit_group;")
#define CP_WAIT0()  asm volatile("cp.async.wait_group 0;")

__device__ __forceinline__ void ldm_x4(uint32_t& r0, uint32_t& r1, uint32_t& r2,
                                       uint32_t& r3, uint32_t addr) {
    asm volatile("ldmatrix.sync.aligned.m8n8.x4.shared.b16 {%0,%1,%2,%3}, [%4];"
                 : "=r"(r0), "=r"(r1), "=r"(r2), "=r"(r3) : "r"(addr));
}

__device__ __forceinline__ void mma_f16(float c[4], uint32_t a0, uint32_t a1,
                                        uint32_t a2, uint32_t a3,
                                        uint32_t b0, uint32_t b1) {
    asm volatile(
        "mma.sync.aligned.m16n8k16.row.col.f32.f16.f16.f32 "
        "{%0,%1,%2,%3}, {%4,%5,%6,%7}, {%8,%9}, {%0,%1,%2,%3};"
        : "+f"(c[0]), "+f"(c[1]), "+f"(c[2]), "+f"(c[3])
        : "r"(a0), "r"(a1), "r"(a2), "r"(a3), "r"(b0), "r"(b1));
}

// ---------------------------------------------------------------------------
// Fused split: search -> hi only; query -> hi+lo; Wk/Wq -> hi only.
// ---------------------------------------------------------------------------
#define N4S (NTOT*EMBED/4)
#define N4Q (BQ*EMBED/4)
#define N4W (EMBED*EMBED/4)

__global__ void split_all(const float* __restrict__ search,
                          const float* __restrict__ query,
                          const float* __restrict__ Wk,
                          const float* __restrict__ Wq) {
    int i = blockIdx.x * blockDim.x + threadIdx.x;
    const float* src;
    __half *hi, *lo = nullptr;
    if (i < N4S)                      { src = search; hi = g_sh_hi; }
    else if ((i -= N4S) < N4Q)        { src = query;  hi = g_qi_hi; lo = g_qi_lo; }
    else if ((i -= N4Q) < N4W)        { src = Wk;     hi = g_wk_hi; }
    else if ((i -= N4W) < N4W)        { src = Wq;     hi = g_wq_hi; }
    else return;
    float4 v = ((const float4*)src)[i];
    __half h0 = __float2half(v.x), h1 = __float2half(v.y);
    __half h2 = __float2half(v.z), h3 = __float2half(v.w);
    ((__half2*)hi)[i*2]   = __halves2half2(h0, h1);
    ((__half2*)hi)[i*2+1] = __halves2half2(h2, h3);
    if (lo) {
        ((__half2*)lo)[i*2]   = __halves2half2(__float2half(v.x - __half2float(h0)),
                                               __float2half(v.y - __half2float(h1)));
        ((__half2*)lo)[i*2+1] = __halves2half2(__float2half(v.z - __half2float(h2)),
                                               __float2half(v.w - __half2float(h3)));
    }
}

// ---------------------------------------------------------------------------
// Projection GEMM (HMMA fp16):
// K-proj (by<128):  C = A_hi @ Wk_hi^T + bk           (1-term)
// Q-proj (by>=128): C = (A_hi + A_lo) @ Wq_hi^T + bq  (2-term)
// K = 768 in 12 chunks of 64. smem/buffer: A_hi 16K | A_lo 16K | B 16K.
// 128 threads, warps 2x2, warp tile 64x64, CTA tile 128x128. 2 CTA/SM.
// ---------------------------------------------------------------------------
__global__ __launch_bounds__(128, 2)
void proj_tc(const float* __restrict__ bk, const float* __restrict__ bq)
{
    extern __shared__ char dsm[];
    const uint32_t sb = smem_u32(dsm);
    const int tid = threadIdx.x, wid = tid >> 5, lane = tid & 31;
    const int wm = wid & 1, wn = wid >> 1;

    const int by = blockIdx.y;
    const int n0 = blockIdx.x * 128;
    const __half *Ahi, *Alo, *Bhi;
    __half *Ohi, *Olo = nullptr;
    const float* bias;
    int m0, nterms;
    bool wlo;
    if (by < 128) { Ahi = g_sh_hi; Alo = nullptr;  Bhi = g_wk_hi;
                    Ohi = g_k_hi;  bias = bk; m0 = by * 128;
                    nterms = 1; wlo = false; }
    else          { Ahi = g_qi_hi; Alo = g_qi_lo; Bhi = g_wq_hi;
                    Ohi = g_qp_hi; Olo = g_qp_lo; bias = bq;
                    m0 = (by - 128) * 128; nterms = 2; wlo = true; }

    float c[4][8][4];
#pragma unroll
    for (int i = 0; i < 4; ++i)
#pragma unroll
        for (int j = 0; j < 8; ++j)
#pragma unroll
            for (int k = 0; k < 4; ++k) c[i][j][k] = 0.0f;

    auto issue = [&](int chunk, int buf) {
        const int k0 = chunk * 64;
        const uint32_t base = sb + (uint32_t)buf * 49152u;
#pragma unroll
        for (int i = 0; i < 8; ++i) {
            const int seg = tid + 128 * i;
            const int row = seg >> 3, sg = seg & 7;
            const uint32_t off = (uint32_t)row * 128u +
                                 ((uint32_t)(sg * 16) ^ (uint32_t)((row & 7) << 4));
            cp16(base + off,          Ahi + (size_t)(m0 + row) * EMBED + k0 + sg * 8);
            if (nterms == 2)
                cp16(base + 16384u + off, Alo + (size_t)(m0 + row) * EMBED + k0 + sg * 8);
            cp16(base + 32768u + off, Bhi + (size_t)(n0 + row) * EMBED + k0 + sg * 8);
        }
        CP_COMMIT();
    };

    issue(0, 0);
    CP_WAIT0();
    __syncthreads();

    const int g  = lane >> 3;
    const int gr = ((g & 1) << 3) + (lane & 7);   // A-frag row sel
    const int gk = (g >> 1) << 4;                 // A-frag k sel
    const int hr = ((g >> 1) << 3) + (lane & 7);  // B-frag row sel
    const int hk = (g & 1) << 4;                  // B-frag k sel

#pragma unroll 1
    for (int ch = 0; ch < 12; ++ch) {
        const int b = ch & 1;
        if (ch + 1 < 12) issue(ch + 1, b ^ 1);

        const uint32_t Ab = sb + (uint32_t)b * 49152u;
        const uint32_t Bb = Ab + 32768u;
#pragma unroll
        for (int ks = 0; ks < 4; ++ks) {
            uint32_t bf[8][2];
#pragma unroll
            for (int p = 0; p < 4; ++p) {
                const int r = wn * 64 + p * 16 + hr;
                const int kb = ks * 32 + hk;
                uint32_t r0, r1, r2, r3;
                ldm_x4(r0, r1, r2, r3,
                       Bb + (uint32_t)r * 128u + (uint32_t)(kb ^ ((r & 7) << 4)));
                bf[2*p][0] = r0;   bf[2*p][1] = r1;
                bf[2*p+1][0] = r2; bf[2*p+1][1] = r3;
            }
#pragma unroll 1
            for (int t = 0; t < nterms; ++t) {
                const uint32_t At = Ab + (uint32_t)t * 16384u;
                uint32_t a[4][4];
#pragma unroll
                for (int mt = 0; mt < 4; ++mt) {
                    const int r = wm * 64 + mt * 16 + gr;
                    const int kb = ks * 32 + gk;
                    ldm_x4(a[mt][0], a[mt][1], a[mt][2], a[mt][3],
                           At + (uint32_t)r * 128u + (uint32_t)(kb ^ ((r & 7) << 4)));
                }
#pragma unroll
                for (int mt = 0; mt < 4; ++mt)
#pragma unroll
                    for (int nt = 0; nt < 8; ++nt)
                        mma_f16(c[mt][nt], a[mt][0], a[mt][1], a[mt][2], a[mt][3],
                                bf[nt][0], bf[nt][1]);
            }
        }
        if (ch + 1 < 12) CP_WAIT0();
        __syncthreads();
    }

    // Epilogue: bias + fp16 split; lo written only for Q-proj.
#pragma unroll
    for (int mt = 0; mt < 4; ++mt) {
#pragma unroll
        for (int nt = 0; nt < 8; ++nt) {
            const int col = n0 + wn * 64 + nt * 8 + (lane & 3) * 2;
            const float bc0 = __ldg(bias + col), bc1 = __ldg(bias + col + 1);
#pragma unroll
            for (int h = 0; h < 2; ++h) {
                const int row = m0 + wm * 64 + mt * 16 + (lane >> 2) + h * 8;
                float x0 = c[mt][nt][2*h]   + bc0;
                float x1 = c[mt][nt][2*h+1] + bc1;
                __half h0 = __float2half(x0), h1 = __float2half(x1);
                *(__half2*)(Ohi + (size_t)row * EMBED + col) = __halves2half2(h0, h1);
                if (wlo) {
                    __half2 ll = __halves2half2(__float2half(x0 - __half2float(h0)),
                                                __float2half(x1 - __half2float(h1)));
                    *(__half2*)(Olo + (size_t)row * EMBED + col) = ll;
                }
            }
        }
    }
}

// ---------------------------------------------------------------------------
// Attention + fused MLP head (HMMA fp16, 2-term):
// logits = (Q_hi + Q_lo) @ K_hi^T. Tile 64(b) x 128(n), 12 chunks of 64.
// Heads = 96 = 6 k16-steps; fold into hp[] via SCALE*W1 at s%6==5.
// smem per buffer: Qhi 8K | Qlo 8K | K 16K = 32K, x2 = 64K; params @65536.
// ---------------------------------------------------------------------------
__global__ __launch_bounds__(256, 1)
void attn_tc(const float* __restrict__ W1, const float* __restrict__ b1,
             const float* __restrict__ W2, const float* __restrict__ b2,
             float* __restrict__ outp)
{
    extern __shared__ char dsm[];
    const uint32_t sb = smem_u32(dsm);
    float* s_w1 = (float*)(dsm + 65536);
    float* s_mi = (float*)(dsm + 65664);
    const int tid = threadIdx.x, wid = tid >> 5, lane = tid & 31;
    const int wm = wid & 1, wn = wid >> 1;

    if (tid < 32) s_w1[tid] = W1[tid] * SCALE;
    if (tid < 4)  { s_mi[tid] = b1[tid]; s_mi[4 + tid] = W2[tid]; }
    if (tid == 8) s_mi[8] = b2[0];

    const int m0 = blockIdx.x * 64;    // b tile (4)
    const int n0 = blockIdx.y * 128;   // n tile (128)

    float c[2][4][4];
    float hp[2][4][4][4];
#pragma unroll
    for (int i = 0; i < 2; ++i)
#pragma unroll
        for (int j = 0; j < 4; ++j)
#pragma unroll
            for (int k = 0; k < 4; ++k) {
                c[i][j][k] = 0.0f;
#pragma unroll
                for (int l = 0; l < 4; ++l) hp[i][j][k][l] = 0.0f;
            }

    auto issue = [&](int chunk, int buf) {
        const int k0 = chunk * 64;
        const uint32_t base = sb + (uint32_t)buf * 32768u;
#pragma unroll
        for (int i = 0; i < 2; ++i) {
            const int seg = tid + 256 * i;
            const int row = seg >> 3, sg = seg & 7;
            const uint32_t off = (uint32_t)row * 128u +
                                 ((uint32_t)(sg * 16) ^ (uint32_t)((row & 7) << 4));
            cp16(base + off,         g_qp_hi + (size_t)(m0 + row) * EMBED + k0 + sg * 8);
            cp16(base + 8192u + off, g_qp_lo + (size_t)(m0 + row) * EMBED + k0 + sg * 8);
        }
#pragma unroll
        for (int i = 0; i < 4; ++i) {
            const int seg = tid + 256 * i;
            const int row = seg >> 3, sg = seg & 7;
            const uint32_t off = (uint32_t)row * 128u +
                                 ((uint32_t)(sg * 16) ^ (uint32_t)((row & 7) << 4));
            cp16(base + 16384u + off, g_k_hi + (size_t)(n0 + row) * EMBED + k0 + sg * 8);
        }
        CP_COMMIT();
    };

    issue(0, 0);
    CP_WAIT0();
    __syncthreads();

    const int g  = lane >> 3;
    const int gr = ((g & 1) << 3) + (lane & 7);
    const int gk = (g >> 1) << 4;
    const int hr = ((g >> 1) << 3) + (lane & 7);
    const int hk = (g & 1) << 4;

#pragma unroll 1
    for (int ch = 0; ch < 12; ++ch) {
        const int b = ch & 1;
        if (ch + 1 < 12) issue(ch + 1, b ^ 1);

        const uint32_t Ab = sb + (uint32_t)b * 32768u;
        const uint32_t Bb = Ab + 16384u;
#pragma unroll
        for (int ks = 0; ks < 4; ++ks) {
            uint32_t bf[4][2];
#pragma unroll
            for (int p = 0; p < 2; ++p) {
                const int r = wn * 32 + p * 16 + hr;
                const int kb = ks * 32 + hk;
                uint32_t r0, r1, r2, r3;
                ldm_x4(r0, r1, r2, r3,
                       Bb + (uint32_t)r * 128u + (uint32_t)(kb ^ ((r & 7) << 4)));
                bf[2*p][0] = r0;   bf[2*p][1] = r1;
                bf[2*p+1][0] = r2; bf[2*p+1][1] = r3;
            }
#pragma unroll
            for (int t = 0; t < 2; ++t) {
                const uint32_t At = Ab + (uint32_t)t * 8192u;
                uint32_t a[2][4];
#pragma unroll
                for (int mt = 0; mt < 2; ++mt) {
                    const int r = wm * 32 + mt * 16 + gr;
                    const int kb = ks * 32 + gk;
                    ldm_x4(a[mt][0], a[mt][1], a[mt][2], a[mt][3],
                           At + (uint32_t)r * 128u + (uint32_t)(kb ^ ((r & 7) << 4)));
                }
#pragma unroll
                for (int mt = 0; mt < 2; ++mt)
#pragma unroll
                    for (int nt = 0; nt < 4; ++nt)
                        mma_f16(c[mt][nt], a[mt][0], a[mt][1], a[mt][2], a[mt][3],
                                bf[nt][0], bf[nt][1]);
            }

            const int s = ch * 4 + ks;
            if ((s % 6) == 5) {            // head boundary: fold into hp
                const int h = s / 6;
                const float w0 = s_w1[h],       w1v = s_w1[8 + h];
                const float w2v = s_w1[16 + h], w3  = s_w1[24 + h];
#pragma unroll
                for (int mt = 0; mt < 2; ++mt)
#pragma unroll
                    for (int nt = 0; nt < 4; ++nt)
#pragma unroll
                        for (int k = 0; k < 4; ++k) {
                            const float v = c[mt][nt][k];
                            hp[mt][nt][k][0] = fmaf(w0,  v, hp[mt][nt][k][0]);
                            hp[mt][nt][k][1] = fmaf(w1v, v, hp[mt][nt][k][1]);
                            hp[mt][nt][k][2] = fmaf(w2v, v, hp[mt][nt][k][2]);
                            hp[mt][nt][k][3] = fmaf(w3,  v, hp[mt][nt][k][3]);
                            c[mt][nt][k] = 0.0f;
                        }
            }
        }
        if (ch + 1 < 12) CP_WAIT0();
        __syncthreads();
    }

    // Epilogue: GELU(erf) + W2, float2 stores
    const float b10 = s_mi[0], b11 = s_mi[1], b12 = s_mi[2], b13 = s_mi[3];
    const float w20 = s_mi[4], w21 = s_mi[5], w22 = s_mi[6], w23 = s_mi[7];
    const float bb2 = s_mi[8];
    const float inv_sqrt2 = 0.70710678118654752f;
#pragma unroll
    for (int mt = 0; mt < 2; ++mt)
#pragma unroll
        for (int nt = 0; nt < 4; ++nt) {
            const int col = n0 + wn * 32 + nt * 8 + (lane & 3) * 2;
#pragma unroll
            for (int h = 0; h < 2; ++h) {
                const int row = m0 + wm * 32 + mt * 16 + (lane >> 2) + h * 8;
                float o[2];
#pragma unroll
                for (int e = 0; e < 2; ++e) {
                    const int k = 2 * h + e;
                    float x0 = hp[mt][nt][k][0] + b10;
                    float x1 = hp[mt][nt][k][1] + b11;
                    float x2 = hp[mt][nt][k][2] + b12;
                    float x3 = hp[mt][nt][k][3] + b13;
                    float g0 = 0.5f * x0 * (1.0f + erff(x0 * inv_sqrt2));
                    float g1 = 0.5f * x1 * (1.0f + erff(x1 * inv_sqrt2));
                    float g2 = 0.5f * x2 * (1.0f + erff(x2 * inv_sqrt2));
                    float g3 = 0.5f * x3 * (1.0f + erff(x3 * inv_sqrt2));
                    float s = bb2;
                    s = fmaf(w20, g0, s); s = fmaf(w21, g1, s);
                    s = fmaf(w22, g2, s); s = fmaf(w23, g3, s);
                    o[e] = s;
                }
                *(float2*)(outp + (size_t)row * NTOT + col) = make_float2(o[0], o[1]);
            }
        }
}

// ---------------------------------------------------------------------------
extern "C" void kernel_launch(void* const* d_in, const int* in_sizes, int n_in,
                              void* d_out, int out_size)
{
    const float* query  = (const float*)d_in[0];
    const float* search = (const float*)d_in[1];
    const float* Wq     = (const float*)d_in[2];
    const float* bq     = (const float*)d_in[3];
    const float* Wk     = (const float*)d_in[4];
    const float* bk     = (const float*)d_in[5];
    const float* W1     = (const float*)d_in[6];
    const float* b1     = (const float*)d_in[7];
    const float* W2     = (const float*)d_in[8];
    const float* b2     = (const float*)d_in[9];
    float* out = (float*)d_out;

    cudaFuncSetAttribute(proj_tc, cudaFuncAttributeMaxDynamicSharedMemorySize, 98304);
    cudaFuncSetAttribute(attn_tc, cudaFuncAttributeMaxDynamicSharedMemorySize, 65792);

    const int total4 = N4S + N4Q + 2 * N4W;
    split_all<<<(total4 + 255) / 256, 256>>>(search, query, Wk, Wq);

    proj_tc<<<dim3(6, 130), 128, 98304>>>(bk, bq);
    attn_tc<<<dim3(4, 128), 256, 65792>>>(W1, b1, W2, b2, out);
}

// round 7
// speedup vs baseline: 4.0561x; 1.1156x over previous
#include <cuda_runtime.h>
#include <cuda_fp16.h>
#include <cstdint>
#include <math.h>

#define EMBED 768
#define BQ    256
#define NTOT  16384
#define SCALE 0.1020620726159657f   // 96^-0.5

// ---------------------------------------------------------------------------
// Device scratch (static globals — no runtime allocation)
// ---------------------------------------------------------------------------
__device__ __half g_sh_hi[NTOT*EMBED];                          // search hi
__device__ __half g_qi_hi[BQ*EMBED],   g_qi_lo[BQ*EMBED];       // query split
__device__ __half g_wk_hi[EMBED*EMBED];                         // Wk hi
__device__ __half g_wq_hi[EMBED*EMBED];                         // Wq hi
__device__ __half g_k_hi[NTOT*EMBED];                           // projected K hi
__device__ __half g_qp_hi[BQ*EMBED];                            // projected Q hi

// ---------------------------------------------------------------------------
// Helpers
// ---------------------------------------------------------------------------
__device__ __forceinline__ uint32_t smem_u32(const void* p) {
    uint32_t a;
    asm("{ .reg .u64 t; cvta.to.shared.u64 t, %1; cvt.u32.u64 %0, t; }"
        : "=r"(a) : "l"(p));
    return a;
}

__device__ __forceinline__ void cp16(uint32_t dst, const void* src) {
    asm volatile("cp.async.cg.shared.global [%0], [%1], 16;" :: "r"(dst), "l"(src));
}
#define CP_COMMIT() asm volatile("cp.async.commit_group;")
#define CP_WAIT0()  asm volatile("cp.async.wait_group 0;")

__device__ __forceinline__ void ldm_x4(uint32_t& r0, uint32_t& r1, uint32_t& r2,
                                       uint32_t& r3, uint32_t addr) {
    asm volatile("ldmatrix.sync.aligned.m8n8.x4.shared.b16 {%0,%1,%2,%3}, [%4];"
                 : "=r"(r0), "=r"(r1), "=r"(r2), "=r"(r3) : "r"(addr));
}

__device__ __forceinline__ void mma_f16(float c[4], uint32_t a0, uint32_t a1,
                                        uint32_t a2, uint32_t a3,
                                        uint32_t b0, uint32_t b1) {
    asm volatile(
        "mma.sync.aligned.m16n8k16.row.col.f32.f16.f16.f32 "
        "{%0,%1,%2,%3}, {%4,%5,%6,%7}, {%8,%9}, {%0,%1,%2,%3};"
        : "+f"(c[0]), "+f"(c[1]), "+f"(c[2]), "+f"(c[3])
        : "r"(a0), "r"(a1), "r"(a2), "r"(a3), "r"(b0), "r"(b1));
}

// ---------------------------------------------------------------------------
// Fused split: search -> hi only; query -> hi+lo; Wk/Wq -> hi only.
// ---------------------------------------------------------------------------
#define N4S (NTOT*EMBED/4)
#define N4Q (BQ*EMBED/4)
#define N4W (EMBED*EMBED/4)

__global__ void split_all(const float* __restrict__ search,
                          const float* __restrict__ query,
                          const float* __restrict__ Wk,
                          const float* __restrict__ Wq) {
    int i = blockIdx.x * blockDim.x + threadIdx.x;
    const float* src;
    __half *hi, *lo = nullptr;
    if (i < N4S)                      { src = search; hi = g_sh_hi; }
    else if ((i -= N4S) < N4Q)        { src = query;  hi = g_qi_hi; lo = g_qi_lo; }
    else if ((i -= N4Q) < N4W)        { src = Wk;     hi = g_wk_hi; }
    else if ((i -= N4W) < N4W)        { src = Wq;     hi = g_wq_hi; }
    else return;
    float4 v = ((const float4*)src)[i];
    __half h0 = __float2half(v.x), h1 = __float2half(v.y);
    __half h2 = __float2half(v.z), h3 = __float2half(v.w);
    ((__half2*)hi)[i*2]   = __halves2half2(h0, h1);
    ((__half2*)hi)[i*2+1] = __halves2half2(h2, h3);
    if (lo) {
        ((__half2*)lo)[i*2]   = __halves2half2(__float2half(v.x - __half2float(h0)),
                                               __float2half(v.y - __half2float(h1)));
        ((__half2*)lo)[i*2+1] = __halves2half2(__float2half(v.z - __half2float(h2)),
                                               __float2half(v.w - __half2float(h3)));
    }
}

// ---------------------------------------------------------------------------
// Projection GEMM (HMMA fp16), persistent CTAs.
// Tile list (780): t in [0,12): Q-proj (2-term, query hi+lo @ Wq_hi);
//                  t in [12,780): K-proj (1-term, search_hi @ Wk_hi).
// CTA tile 128x128, K=768 in 12 chunks of 64, cross-tile double buffering.
// smem/buffer: A_hi 16K | A_lo 16K | B 16K = 48K, x2 = 96K. 2 CTA/SM.
// grid = 296 persistent CTAs; CTA b handles tiles b, b+296, b+592.
// ---------------------------------------------------------------------------
struct TileView {
    const __half *Ahi, *Alo, *Bhi;
    __half* Ohi;
    const float* bias;
    int m0, n0, nterms;
};

__device__ __forceinline__ void tile_params(int t, const float* bk,
                                            const float* bq, TileView& v) {
    if (t < 12) {
        v.Ahi = g_qi_hi; v.Alo = g_qi_lo; v.Bhi = g_wq_hi;
        v.Ohi = g_qp_hi; v.bias = bq;
        v.m0 = (t / 6) * 128; v.n0 = (t % 6) * 128; v.nterms = 2;
    } else {
        const int tt = t - 12;
        v.Ahi = g_sh_hi; v.Alo = nullptr; v.Bhi = g_wk_hi;
        v.Ohi = g_k_hi;  v.bias = bk;
        v.m0 = (tt / 6) * 128; v.n0 = (tt % 6) * 128; v.nterms = 1;
    }
}

__device__ __forceinline__ void proj_issue(uint32_t sb, int buf, int tid,
                                           const TileView& v, int k0) {
    const uint32_t base = sb + (uint32_t)buf * 49152u;
#pragma unroll
    for (int i = 0; i < 8; ++i) {
        const int seg = tid + 128 * i;
        const int row = seg >> 3, sg = seg & 7;
        const uint32_t off = (uint32_t)row * 128u +
                             ((uint32_t)(sg * 16) ^ (uint32_t)((row & 7) << 4));
        cp16(base + off, v.Ahi + (size_t)(v.m0 + row) * EMBED + k0 + sg * 8);
        if (v.nterms == 2)
            cp16(base + 16384u + off, v.Alo + (size_t)(v.m0 + row) * EMBED + k0 + sg * 8);
        cp16(base + 32768u + off, v.Bhi + (size_t)(v.n0 + row) * EMBED + k0 + sg * 8);
    }
    CP_COMMIT();
}

__global__ __launch_bounds__(128, 2)
void proj_tc(const float* __restrict__ bk, const float* __restrict__ bq)
{
    extern __shared__ char dsm[];
    const uint32_t sb = smem_u32(dsm);
    const int tid = threadIdx.x, wid = tid >> 5, lane = tid & 31;
    const int wm = wid & 1, wn = wid >> 1;

    int tl[3]; int ntile = 0;
    for (int t = blockIdx.x; t < 780; t += 296) tl[ntile++] = t;
    if (ntile == 0) return;

    TileView cur, nxt;
    tile_params(tl[0], bk, bq, cur);
    proj_issue(sb, 0, tid, cur, 0);

    const int g  = lane >> 3;
    const int gr = ((g & 1) << 3) + (lane & 7);
    const int gk = (g >> 1) << 4;
    const int hr = ((g >> 1) << 3) + (lane & 7);
    const int hk = (g & 1) << 4;

    int cc = 0;   // global chunk counter (buffer parity)
    CP_WAIT0();
    __syncthreads();

#pragma unroll 1
    for (int ti = 0; ti < ntile; ++ti) {
        tile_params(tl[ti], bk, bq, cur);
        const int nterms = cur.nterms;

        float c[4][8][4];
#pragma unroll
        for (int i = 0; i < 4; ++i)
#pragma unroll
            for (int j = 0; j < 8; ++j)
#pragma unroll
                for (int k = 0; k < 4; ++k) c[i][j][k] = 0.0f;

#pragma unroll 1
        for (int ch = 0; ch < 12; ++ch) {
            const int b = cc & 1;
            ++cc;
            bool issued = false;
            if (ch + 1 < 12) {
                proj_issue(sb, cc & 1, tid, cur, (ch + 1) * 64);
                issued = true;
            } else if (ti + 1 < ntile) {
                tile_params(tl[ti + 1], bk, bq, nxt);
                proj_issue(sb, cc & 1, tid, nxt, 0);
                issued = true;
            }

            const uint32_t Ab = sb + (uint32_t)b * 49152u;
            const uint32_t Bb = Ab + 32768u;
#pragma unroll
            for (int ks = 0; ks < 4; ++ks) {
                uint32_t bf[8][2];
#pragma unroll
                for (int p = 0; p < 4; ++p) {
                    const int r = wn * 64 + p * 16 + hr;
                    const int kb = ks * 32 + hk;
                    uint32_t r0, r1, r2, r3;
                    ldm_x4(r0, r1, r2, r3,
                           Bb + (uint32_t)r * 128u + (uint32_t)(kb ^ ((r & 7) << 4)));
                    bf[2*p][0] = r0;   bf[2*p][1] = r1;
                    bf[2*p+1][0] = r2; bf[2*p+1][1] = r3;
                }
#pragma unroll 1
                for (int t = 0; t < nterms; ++t) {
                    const uint32_t At = Ab + (uint32_t)t * 16384u;
                    uint32_t a[4][4];
#pragma unroll
                    for (int mt = 0; mt < 4; ++mt) {
                        const int r = wm * 64 + mt * 16 + gr;
                        const int kb = ks * 32 + gk;
                        ldm_x4(a[mt][0], a[mt][1], a[mt][2], a[mt][3],
                               At + (uint32_t)r * 128u + (uint32_t)(kb ^ ((r & 7) << 4)));
                    }
#pragma unroll
                    for (int mt = 0; mt < 4; ++mt)
#pragma unroll
                        for (int nt = 0; nt < 8; ++nt)
                            mma_f16(c[mt][nt], a[mt][0], a[mt][1], a[mt][2], a[mt][3],
                                    bf[nt][0], bf[nt][1]);
                }
            }
            if (issued) CP_WAIT0();
            __syncthreads();
        }

        // Epilogue: bias + fp16 hi store (overlaps with next tile's chunk-0 load)
#pragma unroll
        for (int mt = 0; mt < 4; ++mt) {
#pragma unroll
            for (int nt = 0; nt < 8; ++nt) {
                const int col = cur.n0 + wn * 64 + nt * 8 + (lane & 3) * 2;
                const float bc0 = __ldg(cur.bias + col), bc1 = __ldg(cur.bias + col + 1);
#pragma unroll
                for (int h = 0; h < 2; ++h) {
                    const int row = cur.m0 + wm * 64 + mt * 16 + (lane >> 2) + h * 8;
                    float x0 = c[mt][nt][2*h]   + bc0;
                    float x1 = c[mt][nt][2*h+1] + bc1;
                    *(__half2*)(cur.Ohi + (size_t)row * EMBED + col) =
                        __halves2half2(__float2half(x0), __float2half(x1));
                }
            }
        }
    }
}

// ---------------------------------------------------------------------------
// Attention + fused MLP head (HMMA fp16, 1-term):
// logits = Q_hi @ K_hi^T. Tile 64(b) x 128(n), 12 chunks of 64.
// Heads = 96 = 6 k16-steps; fold into hp[] via SCALE*W1 at s%6==5.
// smem per buffer: Q 8K | K 16K = 24K, x2 = 48K; params @49152.
// ---------------------------------------------------------------------------
__global__ __launch_bounds__(256, 1)
void attn_tc(const float* __restrict__ W1, const float* __restrict__ b1,
             const float* __restrict__ W2, const float* __restrict__ b2,
             float* __restrict__ outp)
{
    extern __shared__ char dsm[];
    const uint32_t sb = smem_u32(dsm);
    float* s_w1 = (float*)(dsm + 49152);
    float* s_mi = (float*)(dsm + 49280);
    const int tid = threadIdx.x, wid = tid >> 5, lane = tid & 31;
    const int wm = wid & 1, wn = wid >> 1;

    if (tid < 32) s_w1[tid] = W1[tid] * SCALE;
    if (tid < 4)  { s_mi[tid] = b1[tid]; s_mi[4 + tid] = W2[tid]; }
    if (tid == 8) s_mi[8] = b2[0];

    const int m0 = blockIdx.x * 64;    // b tile (4)
    const int n0 = blockIdx.y * 128;   // n tile (128)

    float c[2][4][4];
    float hp[2][4][4][4];
#pragma unroll
    for (int i = 0; i < 2; ++i)
#pragma unroll
        for (int j = 0; j < 4; ++j)
#pragma unroll
            for (int k = 0; k < 4; ++k) {
                c[i][j][k] = 0.0f;
#pragma unroll
                for (int l = 0; l < 4; ++l) hp[i][j][k][l] = 0.0f;
            }

    auto issue = [&](int chunk, int buf) {
        const int k0 = chunk * 64;
        const uint32_t base = sb + (uint32_t)buf * 24576u;
        {   // Q: 512 segs -> 2 per thread
#pragma unroll
            for (int i = 0; i < 2; ++i) {
                const int seg = tid + 256 * i;
                const int row = seg >> 3, sg = seg & 7;
                const uint32_t off = (uint32_t)row * 128u +
                                     ((uint32_t)(sg * 16) ^ (uint32_t)((row & 7) << 4));
                cp16(base + off, g_qp_hi + (size_t)(m0 + row) * EMBED + k0 + sg * 8);
            }
        }
        {   // K: 1024 segs -> 4 per thread
#pragma unroll
            for (int i = 0; i < 4; ++i) {
                const int seg = tid + 256 * i;
                const int row = seg >> 3, sg = seg & 7;
                const uint32_t off = (uint32_t)row * 128u +
                                     ((uint32_t)(sg * 16) ^ (uint32_t)((row & 7) << 4));
                cp16(base + 8192u + off, g_k_hi + (size_t)(n0 + row) * EMBED + k0 + sg * 8);
            }
        }
        CP_COMMIT();
    };

    issue(0, 0);
    CP_WAIT0();
    __syncthreads();

    const int g  = lane >> 3;
    const int gr = ((g & 1) << 3) + (lane & 7);
    const int gk = (g >> 1) << 4;
    const int hr = ((g >> 1) << 3) + (lane & 7);
    const int hk = (g & 1) << 4;

#pragma unroll 1
    for (int ch = 0; ch < 12; ++ch) {
        const int b = ch & 1;
        if (ch + 1 < 12) issue(ch + 1, b ^ 1);

        const uint32_t Ab = sb + (uint32_t)b * 24576u;
        const uint32_t Bb = Ab + 8192u;
#pragma unroll
        for (int ks = 0; ks < 4; ++ks) {
            uint32_t bf[4][2];
#pragma unroll
            for (int p = 0; p < 2; ++p) {
                const int r = wn * 32 + p * 16 + hr;
                const int kb = ks * 32 + hk;
                uint32_t r0, r1, r2, r3;
                ldm_x4(r0, r1, r2, r3,
                       Bb + (uint32_t)r * 128u + (uint32_t)(kb ^ ((r & 7) << 4)));
                bf[2*p][0] = r0;   bf[2*p][1] = r1;
                bf[2*p+1][0] = r2; bf[2*p+1][1] = r3;
            }
            uint32_t a[2][4];
#pragma unroll
            for (int mt = 0; mt < 2; ++mt) {
                const int r = wm * 32 + mt * 16 + gr;
                const int kb = ks * 32 + gk;
                ldm_x4(a[mt][0], a[mt][1], a[mt][2], a[mt][3],
                       Ab + (uint32_t)r * 128u + (uint32_t)(kb ^ ((r & 7) << 4)));
            }
#pragma unroll
            for (int mt = 0; mt < 2; ++mt)
#pragma unroll
                for (int nt = 0; nt < 4; ++nt)
                    mma_f16(c[mt][nt], a[mt][0], a[mt][1], a[mt][2], a[mt][3],
                            bf[nt][0], bf[nt][1]);

            const int s = ch * 4 + ks;
            if ((s % 6) == 5) {            // head boundary: fold into hp
                const int h = s / 6;
                const float w0 = s_w1[h],       w1v = s_w1[8 + h];
                const float w2v = s_w1[16 + h], w3  = s_w1[24 + h];
#pragma unroll
                for (int mt = 0; mt < 2; ++mt)
#pragma unroll
                    for (int nt = 0; nt < 4; ++nt)
#pragma unroll
                        for (int k = 0; k < 4; ++k) {
                            const float v = c[mt][nt][k];
                            hp[mt][nt][k][0] = fmaf(w0,  v, hp[mt][nt][k][0]);
                            hp[mt][nt][k][1] = fmaf(w1v, v, hp[mt][nt][k][1]);
                            hp[mt][nt][k][2] = fmaf(w2v, v, hp[mt][nt][k][2]);
                            hp[mt][nt][k][3] = fmaf(w3,  v, hp[mt][nt][k][3]);
                            c[mt][nt][k] = 0.0f;
                        }
            }
        }
        if (ch + 1 < 12) CP_WAIT0();
        __syncthreads();
    }

    // Epilogue: GELU(erf) + W2, float2 stores
    const float b10 = s_mi[0], b11 = s_mi[1], b12 = s_mi[2], b13 = s_mi[3];
    const float w20 = s_mi[4], w21 = s_mi[5], w22 = s_mi[6], w23 = s_mi[7];
    const float bb2 = s_mi[8];
    const float inv_sqrt2 = 0.70710678118654752f;
#pragma unroll
    for (int mt = 0; mt < 2; ++mt)
#pragma unroll
        for (int nt = 0; nt < 4; ++nt) {
            const int col = n0 + wn * 32 + nt * 8 + (lane & 3) * 2;
#pragma unroll
            for (int h = 0; h < 2; ++h) {
                const int row = m0 + wm * 32 + mt * 16 + (lane >> 2) + h * 8;
                float o[2];
#pragma unroll
                for (int e = 0; e < 2; ++e) {
                    const int k = 2 * h + e;
                    float x0 = hp[mt][nt][k][0] + b10;
                    float x1 = hp[mt][nt][k][1] + b11;
                    float x2 = hp[mt][nt][k][2] + b12;
                    float x3 = hp[mt][nt][k][3] + b13;
                    float g0 = 0.5f * x0 * (1.0f + erff(x0 * inv_sqrt2));
                    float g1 = 0.5f * x1 * (1.0f + erff(x1 * inv_sqrt2));
                    float g2 = 0.5f * x2 * (1.0f + erff(x2 * inv_sqrt2));
                    float g3 = 0.5f * x3 * (1.0f + erff(x3 * inv_sqrt2));
                    float s = bb2;
                    s = fmaf(w20, g0, s); s = fmaf(w21, g1, s);
                    s = fmaf(w22, g2, s); s = fmaf(w23, g3, s);
                    o[e] = s;
                }
                *(float2*)(outp + (size_t)row * NTOT + col) = make_float2(o[0], o[1]);
            }
        }
}

// ---------------------------------------------------------------------------
extern "C" void kernel_launch(void* const* d_in, const int* in_sizes, int n_in,
                              void* d_out, int out_size)
{
    const float* query  = (const float*)d_in[0];
    const float* search = (const float*)d_in[1];
    const float* Wq     = (const float*)d_in[2];
    const float* bq     = (const float*)d_in[3];
    const float* Wk     = (const float*)d_in[4];
    const float* bk     = (const float*)d_in[5];
    const float* W1     = (const float*)d_in[6];
    const float* b1     = (const float*)d_in[7];
    const float* W2     = (const float*)d_in[8];
    const float* b2     = (const float*)d_in[9];
    float* out = (float*)d_out;

    cudaFuncSetAttribute(proj_tc, cudaFuncAttributeMaxDynamicSharedMemorySize, 98304);
    cudaFuncSetAttribute(attn_tc, cudaFuncAttributeMaxDynamicSharedMemorySize, 49536);

    const int total4 = N4S + N4Q + 2 * N4W;
    split_all<<<(total4 + 255) / 256, 256>>>(search, query, Wk, Wq);

    proj_tc<<<296, 128, 98304>>>(bk, bq);
    attn_tc<<<dim3(4, 128), 256, 49536>>>(W1, b1, W2, b2, out);
}

// round 8
// speedup vs baseline: 4.4755x; 1.1034x over previous
#include <cuda_runtime.h>
#include <cuda_fp16.h>
#include <cstdint>
#include <math.h>

#define EMBED 768
#define BQ    256
#define NTOT  16384
#define SCALE 0.1020620726159657f   // 96^-0.5

#define NPROJ 780        // 12 Q tiles + 768 K tiles
#define NATTN 1024       // 4 b-blocks x 256 n-blocks, 64x64 each
#define NTICK (NPROJ + NATTN)

// ---------------------------------------------------------------------------
// Device scratch (static globals — no runtime allocation)
// ---------------------------------------------------------------------------
__device__ __half g_sh_hi[NTOT*EMBED];                          // search hi
__device__ __half g_qi_hi[BQ*EMBED],   g_qi_lo[BQ*EMBED];       // query split
__device__ __half g_wk_hi[EMBED*EMBED];                         // Wk hi
__device__ __half g_wq_hi[EMBED*EMBED];                         // Wq hi
__device__ __half g_k_hi[NTOT*EMBED];                           // projected K hi
__device__ __half g_qp_hi[BQ*EMBED];                            // projected Q hi

__device__ int g_ticket;
__device__ int g_kdone[128];   // per K m-block (128 rows each): count to 6
__device__ int g_qdone[2];     // per Q m-block: count to 6

// ---------------------------------------------------------------------------
// Helpers
// ---------------------------------------------------------------------------
__device__ __forceinline__ uint32_t smem_u32(const void* p) {
    uint32_t a;
    asm("{ .reg .u64 t; cvta.to.shared.u64 t, %1; cvt.u32.u64 %0, t; }"
        : "=r"(a) : "l"(p));
    return a;
}

__device__ __forceinline__ void cp16(uint32_t dst, const void* src) {
    asm volatile("cp.async.cg.shared.global [%0], [%1], 16;" :: "r"(dst), "l"(src));
}
#define CP_COMMIT() asm volatile("cp.async.commit_group;")
#define CP_WAIT0()  asm volatile("cp.async.wait_group 0;")

__device__ __forceinline__ void ldm_x4(uint32_t& r0, uint32_t& r1, uint32_t& r2,
                                       uint32_t& r3, uint32_t addr) {
    asm volatile("ldmatrix.sync.aligned.m8n8.x4.shared.b16 {%0,%1,%2,%3}, [%4];"
                 : "=r"(r0), "=r"(r1), "=r"(r2), "=r"(r3) : "r"(addr));
}

__device__ __forceinline__ void mma_f16(float c[4], uint32_t a0, uint32_t a1,
                                        uint32_t a2, uint32_t a3,
                                        uint32_t b0, uint32_t b1) {
    asm volatile(
        "mma.sync.aligned.m16n8k16.row.col.f32.f16.f16.f32 "
        "{%0,%1,%2,%3}, {%4,%5,%6,%7}, {%8,%9}, {%0,%1,%2,%3};"
        : "+f"(c[0]), "+f"(c[1]), "+f"(c[2]), "+f"(c[3])
        : "r"(a0), "r"(a1), "r"(a2), "r"(a3), "r"(b0), "r"(b1));
}

// ---------------------------------------------------------------------------
// Fused split + flag reset.
// search -> hi only; query -> hi+lo; Wk/Wq -> hi only.
// ---------------------------------------------------------------------------
#define N4S (NTOT*EMBED/4)
#define N4Q (BQ*EMBED/4)
#define N4W (EMBED*EMBED/4)

__global__ void split_all(const float* __restrict__ search,
                          const float* __restrict__ query,
                          const float* __restrict__ Wk,
                          const float* __restrict__ Wq) {
    if (blockIdx.x == 0) {          // reset queue + flags (distinct arrays)
        if (threadIdx.x == 0) g_ticket = 0;
        if (threadIdx.x < 128) g_kdone[threadIdx.x] = 0;
        if (threadIdx.x < 2)   g_qdone[threadIdx.x] = 0;
    }
    int i = blockIdx.x * blockDim.x + threadIdx.x;
    const float* src;
    __half *hi, *lo = nullptr;
    if (i < N4S)                      { src = search; hi = g_sh_hi; }
    else if ((i -= N4S) < N4Q)        { src = query;  hi = g_qi_hi; lo = g_qi_lo; }
    else if ((i -= N4Q) < N4W)        { src = Wk;     hi = g_wk_hi; }
    else if ((i -= N4W) < N4W)        { src = Wq;     hi = g_wq_hi; }
    else return;
    float4 v = ((const float4*)src)[i];
    __half h0 = __float2half(v.x), h1 = __float2half(v.y);
    __half h2 = __float2half(v.z), h3 = __float2half(v.w);
    ((__half2*)hi)[i*2]   = __halves2half2(h0, h1);
    ((__half2*)hi)[i*2+1] = __halves2half2(h2, h3);
    if (lo) {
        ((__half2*)lo)[i*2]   = __halves2half2(__float2half(v.x - __half2float(h0)),
                                               __float2half(v.y - __half2float(h1)));
        ((__half2*)lo)[i*2+1] = __halves2half2(__float2half(v.z - __half2float(h2)),
                                               __float2half(v.w - __half2float(h3)));
    }
}

// ---------------------------------------------------------------------------
// Fused persistent kernel: proj tiles (tickets 0..779) + attn tiles (780..).
// 296 CTAs x 128 threads, 2 CTA/SM (all resident -> spin-safe).
// smem: proj buffers A/Alo/B @ buf*49152 (96K) | params @98304 | tick @98560.
// ---------------------------------------------------------------------------
struct TileView {
    const __half *Ahi, *Alo, *Bhi;
    __half* Ohi;
    const float* bias;
    int m0, n0, nterms;
};

__device__ __forceinline__ void tile_params(int t, const float* bk,
                                            const float* bq, TileView& v) {
    if (t < 12) {
        v.Ahi = g_qi_hi; v.Alo = g_qi_lo; v.Bhi = g_wq_hi;
        v.Ohi = g_qp_hi; v.bias = bq;
        v.m0 = (t / 6) * 128; v.n0 = (t % 6) * 128; v.nterms = 2;
    } else {
        const int tt = t - 12;
        v.Ahi = g_sh_hi; v.Alo = nullptr; v.Bhi = g_wk_hi;
        v.Ohi = g_k_hi;  v.bias = bk;
        v.m0 = (tt / 6) * 128; v.n0 = (tt % 6) * 128; v.nterms = 1;
    }
}

__device__ __forceinline__ void proj_issue(uint32_t sb, int buf, int tid,
                                           const TileView& v, int k0) {
    const uint32_t base = sb + (uint32_t)buf * 49152u;
#pragma unroll
    for (int i = 0; i < 8; ++i) {
        const int seg = tid + 128 * i;
        const int row = seg >> 3, sg = seg & 7;
        const uint32_t off = (uint32_t)row * 128u +
                             ((uint32_t)(sg * 16) ^ (uint32_t)((row & 7) << 4));
        cp16(base + off, v.Ahi + (size_t)(v.m0 + row) * EMBED + k0 + sg * 8);
        if (v.nterms == 2)
            cp16(base + 16384u + off, v.Alo + (size_t)(v.m0 + row) * EMBED + k0 + sg * 8);
        cp16(base + 32768u + off, v.Bhi + (size_t)(v.n0 + row) * EMBED + k0 + sg * 8);
    }
    CP_COMMIT();
}

__global__ __launch_bounds__(128, 2)
void fused_tc(const float* __restrict__ bk, const float* __restrict__ bq,
              const float* __restrict__ W1, const float* __restrict__ b1,
              const float* __restrict__ W2, const float* __restrict__ b2,
              float* __restrict__ outp)
{
    extern __shared__ char dsm[];
    const uint32_t sb = smem_u32(dsm);
    float* s_w1 = (float*)(dsm + 98304);
    float* s_mi = (float*)(dsm + 98432);
    int*   s_tk = (int*)(dsm + 98560);
    const int tid = threadIdx.x, wid = tid >> 5, lane = tid & 31;
    const int wm = wid & 1, wn = wid >> 1;

    if (tid < 32) s_w1[tid] = W1[tid] * SCALE;
    if (tid < 4)  { s_mi[tid] = b1[tid]; s_mi[4 + tid] = W2[tid]; }
    if (tid == 8) s_mi[8] = b2[0];

    const int g  = lane >> 3;
    const int gr = ((g & 1) << 3) + (lane & 7);   // A-frag row sel
    const int gk = (g >> 1) << 4;                 // A-frag k sel
    const int hr = ((g >> 1) << 3) + (lane & 7);  // B-frag row sel
    const int hk = (g & 1) << 4;                  // B-frag k sel

    __syncthreads();

    for (;;) {
        if (tid == 0) *s_tk = atomicAdd(&g_ticket, 1);
        __syncthreads();
        const int t = *s_tk;
        __syncthreads();
        if (t >= NTICK) break;

        if (t < NPROJ) {
            // ============================ PROJ TILE ============================
            TileView v;
            tile_params(t, bk, bq, v);
            const int nterms = v.nterms;

            float c[4][8][4];
#pragma unroll
            for (int i = 0; i < 4; ++i)
#pragma unroll
                for (int j = 0; j < 8; ++j)
#pragma unroll
                    for (int k = 0; k < 4; ++k) c[i][j][k] = 0.0f;

            proj_issue(sb, 0, tid, v, 0);
            CP_WAIT0();
            __syncthreads();

#pragma unroll 1
            for (int ch = 0; ch < 12; ++ch) {
                const int b = ch & 1;
                if (ch + 1 < 12) proj_issue(sb, b ^ 1, tid, v, (ch + 1) * 64);

                const uint32_t Ab = sb + (uint32_t)b * 49152u;
                const uint32_t Bb = Ab + 32768u;
#pragma unroll
                for (int ks = 0; ks < 4; ++ks) {
                    uint32_t bf[8][2];
#pragma unroll
                    for (int p = 0; p < 4; ++p) {
                        const int r = wn * 64 + p * 16 + hr;
                        const int kb = ks * 32 + hk;
                        uint32_t r0, r1, r2, r3;
                        ldm_x4(r0, r1, r2, r3,
                               Bb + (uint32_t)r * 128u + (uint32_t)(kb ^ ((r & 7) << 4)));
                        bf[2*p][0] = r0;   bf[2*p][1] = r1;
                        bf[2*p+1][0] = r2; bf[2*p+1][1] = r3;
                    }
#pragma unroll 1
                    for (int tt = 0; tt < nterms; ++tt) {
                        const uint32_t At = Ab + (uint32_t)tt * 16384u;
                        uint32_t a[4][4];
#pragma unroll
                        for (int mt = 0; mt < 4; ++mt) {
                            const int r = wm * 64 + mt * 16 + gr;
                            const int kb = ks * 32 + gk;
                            ldm_x4(a[mt][0], a[mt][1], a[mt][2], a[mt][3],
                                   At + (uint32_t)r * 128u + (uint32_t)(kb ^ ((r & 7) << 4)));
                        }
#pragma unroll
                        for (int mt = 0; mt < 4; ++mt)
#pragma unroll
                            for (int nt = 0; nt < 8; ++nt)
                                mma_f16(c[mt][nt], a[mt][0], a[mt][1], a[mt][2], a[mt][3],
                                        bf[nt][0], bf[nt][1]);
                    }
                }
                if (ch + 1 < 12) CP_WAIT0();
                __syncthreads();
            }

            // Epilogue: bias + fp16 hi store
#pragma unroll
            for (int mt = 0; mt < 4; ++mt) {
#pragma unroll
                for (int nt = 0; nt < 8; ++nt) {
                    const int col = v.n0 + wn * 64 + nt * 8 + (lane & 3) * 2;
                    const float bc0 = __ldg(v.bias + col), bc1 = __ldg(v.bias + col + 1);
#pragma unroll
                    for (int h = 0; h < 2; ++h) {
                        const int row = v.m0 + wm * 64 + mt * 16 + (lane >> 2) + h * 8;
                        float x0 = c[mt][nt][2*h]   + bc0;
                        float x1 = c[mt][nt][2*h+1] + bc1;
                        *(__half2*)(v.Ohi + (size_t)row * EMBED + col) =
                            __halves2half2(__float2half(x0), __float2half(x1));
                    }
                }
            }

            // publish: all stores visible, then count the tile
            __threadfence();
            __syncthreads();
            if (tid == 0) {
                if (t < 12) atomicAdd(&g_qdone[t / 6], 1);
                else        atomicAdd(&g_kdone[(t - 12) / 6], 1);
            }
        } else {
            // ============================ ATTN TILE ============================
            const int u  = t - NPROJ;
            const int bb = u & 3, nb = u >> 2;
            const int m0 = bb * 64, n0 = nb * 64;

            // wait for producers (K m-block nb>>1, Q m-block bb>>1)
            if (tid == 0) {
                while (atomicAdd(&g_kdone[nb >> 1], 0) < 6) __nanosleep(64);
                while (atomicAdd(&g_qdone[bb >> 1], 0) < 6) __nanosleep(64);
            }
            __syncthreads();

            float c[2][4][4];
            float hp[2][4][4][4];
#pragma unroll
            for (int i = 0; i < 2; ++i)
#pragma unroll
                for (int j = 0; j < 4; ++j)
#pragma unroll
                    for (int k = 0; k < 4; ++k) {
                        c[i][j][k] = 0.0f;
#pragma unroll
                        for (int l = 0; l < 4; ++l) hp[i][j][k][l] = 0.0f;
                    }

            auto issue = [&](int chunk, int buf) {
                const int k0 = chunk * 64;
                const uint32_t base = sb + (uint32_t)buf * 49152u;
#pragma unroll
                for (int i = 0; i < 4; ++i) {        // Q 512 segs + K 512 segs
                    const int seg = tid + 128 * i;
                    const int row = seg >> 3, sg = seg & 7;
                    const uint32_t off = (uint32_t)row * 128u +
                                         ((uint32_t)(sg * 16) ^ (uint32_t)((row & 7) << 4));
                    cp16(base + off,         g_qp_hi + (size_t)(m0 + row) * EMBED + k0 + sg * 8);
                    cp16(base + 8192u + off, g_k_hi  + (size_t)(n0 + row) * EMBED + k0 + sg * 8);
                }
                CP_COMMIT();
            };

            issue(0, 0);
            CP_WAIT0();
            __syncthreads();

#pragma unroll 1
            for (int ch = 0; ch < 12; ++ch) {
                const int b = ch & 1;
                if (ch + 1 < 12) issue(ch + 1, b ^ 1);

                const uint32_t Ab = sb + (uint32_t)b * 49152u;
                const uint32_t Bb = Ab + 8192u;
#pragma unroll
                for (int ks = 0; ks < 4; ++ks) {
                    uint32_t bf[4][2];
#pragma unroll
                    for (int p = 0; p < 2; ++p) {
                        const int r = wn * 32 + p * 16 + hr;
                        const int kb = ks * 32 + hk;
                        uint32_t r0, r1, r2, r3;
                        ldm_x4(r0, r1, r2, r3,
                               Bb + (uint32_t)r * 128u + (uint32_t)(kb ^ ((r & 7) << 4)));
                        bf[2*p][0] = r0;   bf[2*p][1] = r1;
                        bf[2*p+1][0] = r2; bf[2*p+1][1] = r3;
                    }
                    uint32_t a[2][4];
#pragma unroll
                    for (int mt = 0; mt < 2; ++mt) {
                        const int r = wm * 32 + mt * 16 + gr;
                        const int kb = ks * 32 + gk;
                        ldm_x4(a[mt][0], a[mt][1], a[mt][2], a[mt][3],
                               Ab + (uint32_t)r * 128u + (uint32_t)(kb ^ ((r & 7) << 4)));
                    }
#pragma unroll
                    for (int mt = 0; mt < 2; ++mt)
#pragma unroll
                        for (int nt = 0; nt < 4; ++nt)
                            mma_f16(c[mt][nt], a[mt][0], a[mt][1], a[mt][2], a[mt][3],
                                    bf[nt][0], bf[nt][1]);

                    const int s = ch * 4 + ks;
                    if ((s % 6) == 5) {           // head boundary: fold into hp
                        const int h = s / 6;
                        const float w0 = s_w1[h],       w1v = s_w1[8 + h];
                        const float w2v = s_w1[16 + h], w3  = s_w1[24 + h];
#pragma unroll
                        for (int mt = 0; mt < 2; ++mt)
#pragma unroll
                            for (int nt = 0; nt < 4; ++nt)
#pragma unroll
                                for (int k = 0; k < 4; ++k) {
                                    const float vv = c[mt][nt][k];
                                    hp[mt][nt][k][0] = fmaf(w0,  vv, hp[mt][nt][k][0]);
                                    hp[mt][nt][k][1] = fmaf(w1v, vv, hp[mt][nt][k][1]);
                                    hp[mt][nt][k][2] = fmaf(w2v, vv, hp[mt][nt][k][2]);
                                    hp[mt][nt][k][3] = fmaf(w3,  vv, hp[mt][nt][k][3]);
                                    c[mt][nt][k] = 0.0f;
                                }
                    }
                }
                if (ch + 1 < 12) CP_WAIT0();
                __syncthreads();
            }

            // Epilogue: GELU(erf) + W2, float2 stores
            const float b10 = s_mi[0], b11 = s_mi[1], b12 = s_mi[2], b13 = s_mi[3];
            const float w20 = s_mi[4], w21 = s_mi[5], w22 = s_mi[6], w23 = s_mi[7];
            const float bb2 = s_mi[8];
            const float inv_sqrt2 = 0.70710678118654752f;
#pragma unroll
            for (int mt = 0; mt < 2; ++mt)
#pragma unroll
                for (int nt = 0; nt < 4; ++nt) {
                    const int col = n0 + wn * 32 + nt * 8 + (lane & 3) * 2;
#pragma unroll
                    for (int h = 0; h < 2; ++h) {
                        const int row = m0 + wm * 32 + mt * 16 + (lane >> 2) + h * 8;
                        float o[2];
#pragma unroll
                        for (int e = 0; e < 2; ++e) {
                            const int k = 2 * h + e;
                            float x0 = hp[mt][nt][k][0] + b10;
                            float x1 = hp[mt][nt][k][1] + b11;
                            float x2 = hp[mt][nt][k][2] + b12;
                            float x3 = hp[mt][nt][k][3] + b13;
                            float g0 = 0.5f * x0 * (1.0f + erff(x0 * inv_sqrt2));
                            float g1 = 0.5f * x1 * (1.0f + erff(x1 * inv_sqrt2));
                            float g2 = 0.5f * x2 * (1.0f + erff(x2 * inv_sqrt2));
                            float g3 = 0.5f * x3 * (1.0f + erff(x3 * inv_sqrt2));
                            float s = bb2;
                            s = fmaf(w20, g0, s); s = fmaf(w21, g1, s);
                            s = fmaf(w22, g2, s); s = fmaf(w23, g3, s);
                            o[e] = s;
                        }
                        *(float2*)(outp + (size_t)row * NTOT + col) = make_float2(o[0], o[1]);
                    }
                }
        }
    }
}

// ---------------------------------------------------------------------------
extern "C" void kernel_launch(void* const* d_in, const int* in_sizes, int n_in,
                              void* d_out, int out_size)
{
    const float* query  = (const float*)d_in[0];
    const float* search = (const float*)d_in[1];
    const float* Wq     = (const float*)d_in[2];
    const float* bq     = (const float*)d_in[3];
    const float* Wk     = (const float*)d_in[4];
    const float* bk     = (const float*)d_in[5];
    const float* W1     = (const float*)d_in[6];
    const float* b1     = (const float*)d_in[7];
    const float* W2     = (const float*)d_in[8];
    const float* b2     = (const float*)d_in[9];
    float* out = (float*)d_out;

    cudaFuncSetAttribute(fused_tc, cudaFuncAttributeMaxDynamicSharedMemorySize, 98816);

    const int total4 = N4S + N4Q + 2 * N4W;
    split_all<<<(total4 + 255) / 256, 256>>>(search, query, Wk, Wq);

    fused_tc<<<296, 128, 98816>>>(bk, bq, W1, b1, W2, b2, out);
}